// round 1
// baseline (speedup 1.0000x reference)
#include <cuda_runtime.h>
#include <math.h>
#include <stdint.h>

#define T_STEPS 12
#define IN_DIM  64
#define HID_DIM 128
#define EMB_DIM 64
#define NMAX    10000
#define EMAX    320000
#define ETOT    (EMAX + NMAX)

// ---------------- scratch (device globals; no allocation allowed) ----------------
__device__ float g_deg[NMAX];
__device__ float g_dinv[NMAX];
__device__ int   g_cnt[NMAX];
__device__ int   g_fill[NMAX];
__device__ int   g_ptr[NMAX + 1];
__device__ int   g_src[ETOT];
__device__ float g_val[ETOT];
__device__ int   g_idx32;  // 1 if edge_index is int32, 0 if int64

__device__ float g_aggx[(size_t)T_STEPS * NMAX * IN_DIM];   // reused later as P
__device__ float g_h1  [(size_t)T_STEPS * NMAX * HID_DIM];
__device__ float g_zseq[(size_t)T_STEPS * NMAX * EMB_DIM];
__device__ float g_gi  [(size_t)T_STEPS * NMAX * 3 * EMB_DIM];
__device__ float g_h   [(size_t)NMAX * EMB_DIM];

// ---------------- helpers ----------------
__device__ __forceinline__ int load_idx(const void* ei, long long i) {
    if (g_idx32) return ((const int*)ei)[i];
    return (int)(((const long long*)ei)[i]);
}

// ---------------- preprocessing ----------------
__global__ void zero_pre_kernel(int N) {
    int i = blockIdx.x * blockDim.x + threadIdx.x;
    if (i < N) { g_deg[i] = 0.f; g_cnt[i] = 0; g_fill[i] = 0; }
    if (i == 0) g_idx32 = 0;
}

// Detect int32 vs int64 edge_index. Reading first E int64 slots is safe in both
// layouts (int32 buffer holds 2E int32 = E int64s of bytes). Legit int64 values
// are all in [0,N); int32-reinterp pairs are almost surely out of range.
__global__ void detect_kernel(const void* ei, int E, int N) {
    int i = blockIdx.x * blockDim.x + threadIdx.x;
    if (i >= E) return;
    long long v = ((const long long*)ei)[i];
    if (v < 0 || v >= (long long)N) atomicOr(&g_idx32, 1);
}

__global__ void deg_kernel(const void* ei, const float* __restrict__ ew, int E, int N) {
    int i = blockIdx.x * blockDim.x + threadIdx.x;
    if (i < E) {
        int c = load_idx(ei, (long long)E + i);
        atomicAdd(&g_deg[c], ew[i]);
        atomicAdd(&g_cnt[c], 1);
    } else if (i < E + N) {
        int v = i - E;
        atomicAdd(&g_deg[v], 1.0f);   // self loop weight 1
        atomicAdd(&g_cnt[v], 1);
    }
}

__global__ void dinv_kernel(int N) {
    int i = blockIdx.x * blockDim.x + threadIdx.x;
    if (i < N) {
        float d = g_deg[i];
        g_dinv[i] = (d > 0.f) ? rsqrtf(d) : 0.f;
    }
}

// single-block exclusive scan: g_cnt -> g_ptr
__global__ void scan_kernel(int n) {
    __shared__ int sh[1024];
    int tid = threadIdx.x;
    int carry = 0;
    for (int base = 0; base < n; base += 1024) {
        int v = (base + tid < n) ? g_cnt[base + tid] : 0;
        sh[tid] = v;
        __syncthreads();
        #pragma unroll
        for (int off = 1; off < 1024; off <<= 1) {
            int t = (tid >= off) ? sh[tid - off] : 0;
            __syncthreads();
            sh[tid] += t;
            __syncthreads();
        }
        if (base + tid < n) g_ptr[base + tid] = carry + sh[tid] - v;
        carry += sh[1023];
        __syncthreads();
    }
    if (tid == 0) g_ptr[n] = carry;
}

__global__ void scatter_kernel(const void* ei, const float* __restrict__ ew, int E, int N) {
    int i = blockIdx.x * blockDim.x + threadIdx.x;
    if (i < E) {
        int r = load_idx(ei, i);
        int c = load_idx(ei, (long long)E + i);
        int p = g_ptr[c] + atomicAdd(&g_fill[c], 1);
        g_src[p] = r;
        g_val[p] = g_dinv[r] * ew[i] * g_dinv[c];
    } else if (i < E + N) {
        int v = i - E;
        int p = g_ptr[v] + atomicAdd(&g_fill[v], 1);
        g_src[p] = v;
        g_val[p] = g_dinv[v] * g_dinv[v];
    }
}

// ---------------- batched (over T) 64-dim aggregation: dst[t][c] = sum_e val*src[t][row] ----------------
__global__ void agg_kernel(const float* __restrict__ src, float* __restrict__ dst,
                           const float* __restrict__ bias, int N) {
    int warp = (blockIdx.x * blockDim.x + threadIdx.x) >> 5;
    int lane = threadIdx.x & 31;
    if (warp >= N) return;
    int e0 = g_ptr[warp], e1 = g_ptr[warp + 1];
    float2 acc[T_STEPS];
    #pragma unroll
    for (int t = 0; t < T_STEPS; t++) { acc[t].x = 0.f; acc[t].y = 0.f; }
    const int tstride2 = N * 32;  // float2 elems per timestep (N*64/2)
    for (int e = e0; e < e1; e += 32) {
        int got = e1 - e; if (got > 32) got = 32;
        int r = 0; float v = 0.f;
        if (lane < got) { r = g_src[e + lane]; v = g_val[e + lane]; }
        for (int j = 0; j < got; j++) {
            int   rr = __shfl_sync(0xffffffffu, r, j);
            float vv = __shfl_sync(0xffffffffu, v, j);
            const float2* xp = reinterpret_cast<const float2*>(src + (size_t)rr * 64) + lane;
            #pragma unroll
            for (int t = 0; t < T_STEPS; t++) {
                float2 xv = xp[t * tstride2];
                acc[t].x = fmaf(vv, xv.x, acc[t].x);
                acc[t].y = fmaf(vv, xv.y, acc[t].y);
            }
        }
    }
    float bx = 0.f, by = 0.f;
    if (bias) { bx = bias[2 * lane]; by = bias[2 * lane + 1]; }
    #pragma unroll
    for (int t = 0; t < T_STEPS; t++) {
        float2 o; o.x = acc[t].x + bx; o.y = acc[t].y + by;
        *reinterpret_cast<float2*>(dst + (size_t)t * N * 64 + (size_t)warp * 64 + 2 * lane) = o;
    }
}

// ---------------- generic SGEMM: C[M,N] = A[M,K] @ B + epilogue ----------------
// transB=0: B is [K,N] row-major. transB=1: B is [N,K] row-major.
// epi: 0 none, 1 bias+relu, 2 bias, 3 softplus(x + bias[0])
__global__ __launch_bounds__(256) void sgemm_kernel(
    const float* __restrict__ A, const float* __restrict__ B, float* __restrict__ C,
    int M, int N, int K, const float* __restrict__ bias, int epi, int transB)
{
    __shared__ __align__(16) float As[8][128];
    __shared__ __align__(16) float Bs[8][128];
    const int tid = threadIdx.x;
    const int bm = blockIdx.y * 128;
    const int bn = blockIdx.x * 128;
    const int tr = (tid / 16) * 8;
    const int tc = (tid % 16) * 8;

    float acc[8][8];
    #pragma unroll
    for (int i = 0; i < 8; i++)
        #pragma unroll
        for (int j = 0; j < 8; j++) acc[i][j] = 0.f;

    const int arow = tid >> 1;
    const int acol = (tid & 1) * 4;

    for (int kt = 0; kt < K; kt += 8) {
        float4 av = make_float4(0.f, 0.f, 0.f, 0.f);
        if (bm + arow < M)
            av = *reinterpret_cast<const float4*>(A + (size_t)(bm + arow) * K + kt + acol);
        As[acol + 0][arow] = av.x; As[acol + 1][arow] = av.y;
        As[acol + 2][arow] = av.z; As[acol + 3][arow] = av.w;

        if (!transB) {
            int kr = tid >> 5;
            int cc = (tid & 31) * 4;
            float4 bv = make_float4(0.f, 0.f, 0.f, 0.f);
            if (bn + cc < N)
                bv = *reinterpret_cast<const float4*>(B + (size_t)(kt + kr) * N + bn + cc);
            *reinterpret_cast<float4*>(&Bs[kr][cc]) = bv;
        } else {
            int cc = tid >> 1;
            int kk = (tid & 1) * 4;
            float4 bv = make_float4(0.f, 0.f, 0.f, 0.f);
            if (bn + cc < N)
                bv = *reinterpret_cast<const float4*>(B + (size_t)(bn + cc) * K + kt + kk);
            Bs[kk + 0][cc] = bv.x; Bs[kk + 1][cc] = bv.y;
            Bs[kk + 2][cc] = bv.z; Bs[kk + 3][cc] = bv.w;
        }
        __syncthreads();

        #pragma unroll
        for (int k = 0; k < 8; k++) {
            float ar[8], br[8];
            *reinterpret_cast<float4*>(ar)     = *reinterpret_cast<const float4*>(&As[k][tr]);
            *reinterpret_cast<float4*>(ar + 4) = *reinterpret_cast<const float4*>(&As[k][tr + 4]);
            *reinterpret_cast<float4*>(br)     = *reinterpret_cast<const float4*>(&Bs[k][tc]);
            *reinterpret_cast<float4*>(br + 4) = *reinterpret_cast<const float4*>(&Bs[k][tc + 4]);
            #pragma unroll
            for (int i = 0; i < 8; i++)
                #pragma unroll
                for (int j = 0; j < 8; j++)
                    acc[i][j] = fmaf(ar[i], br[j], acc[i][j]);
        }
        __syncthreads();
    }

    float bsc = 0.f;
    if (epi == 3 && bias) bsc = bias[0];

    #pragma unroll
    for (int i = 0; i < 8; i++) {
        int r = bm + tr + i;
        if (r >= M) continue;
        #pragma unroll
        for (int jj = 0; jj < 8; jj += 4) {
            int c = bn + tc + jj;
            if (c >= N) continue;   // N is always a multiple of 4; tc+jj aligned 4
            float4 v4;
            float* vp = reinterpret_cast<float*>(&v4);
            #pragma unroll
            for (int q = 0; q < 4; q++) {
                float v = acc[i][jj + q];
                if (epi == 1)      { v += bias[c + q]; v = fmaxf(v, 0.f); }
                else if (epi == 2) { v += bias[c + q]; }
                else if (epi == 3) {
                    v += bsc;
                    v = fmaxf(v, 0.f) + log1pf(__expf(-fabsf(v)));
                }
                vp[q] = v;
            }
            *reinterpret_cast<float4*>(C + (size_t)r * N + c) = v4;
        }
    }
}

// ---------------- GRU recurrent step (gi precomputed) ----------------
__global__ __launch_bounds__(256) void gru_kernel(
    const float* __restrict__ gi,    // [N,192] for this t (includes b_ih)
    const float* __restrict__ Whh,   // [192,64]
    const float* __restrict__ bhh,   // [192]
    float* __restrict__ h, int N)
{
    __shared__ __align__(16) float sh_h[4][EMB_DIM];
    int tid = threadIdx.x;
    int c = tid & 63, rs = tid >> 6;
    int row = blockIdx.x * 4 + rs;
    if (row < N) sh_h[rs][c] = h[(size_t)row * EMB_DIM + c];
    __syncthreads();
    if (row >= N) return;

    float accr = bhh[c], accz = bhh[64 + c], accn = bhh[128 + c];
    const float* hr = sh_h[rs];
    #pragma unroll
    for (int k = 0; k < 64; k += 4) {
        float4 hv = *reinterpret_cast<const float4*>(hr + k);
        float4 wr = *reinterpret_cast<const float4*>(Whh + (size_t)c * 64 + k);
        float4 wz = *reinterpret_cast<const float4*>(Whh + (size_t)(64 + c) * 64 + k);
        float4 wn = *reinterpret_cast<const float4*>(Whh + (size_t)(128 + c) * 64 + k);
        accr = fmaf(hv.x, wr.x, accr); accr = fmaf(hv.y, wr.y, accr);
        accr = fmaf(hv.z, wr.z, accr); accr = fmaf(hv.w, wr.w, accr);
        accz = fmaf(hv.x, wz.x, accz); accz = fmaf(hv.y, wz.y, accz);
        accz = fmaf(hv.z, wz.z, accz); accz = fmaf(hv.w, wz.w, accz);
        accn = fmaf(hv.x, wn.x, accn); accn = fmaf(hv.y, wn.y, accn);
        accn = fmaf(hv.z, wn.z, accn); accn = fmaf(hv.w, wn.w, accn);
    }
    const float* gir = gi + (size_t)row * 192;
    float rg = 1.f / (1.f + __expf(-(gir[c]      + accr)));
    float zg = 1.f / (1.f + __expf(-(gir[64 + c] + accz)));
    float ng = tanhf(gir[128 + c] + rg * accn);
    float hold = hr[c];
    h[(size_t)row * EMB_DIM + c] = (1.f - zg) * ng + zg * hold;
}

__global__ void zero_f_kernel(float* p, long long n) {
    long long i = (long long)blockIdx.x * blockDim.x + threadIdx.x;
    if (i < n) p[i] = 0.f;
}

__global__ void copy_z_kernel(float* __restrict__ out, int n) {
    int i = blockIdx.x * blockDim.x + threadIdx.x;
    if (i < n) out[i] = g_h[i];
}

// ---------------- launch ----------------
extern "C" void kernel_launch(void* const* d_in, const int* in_sizes, int n_in,
                              void* d_out, int out_size) {
    const float* x_seq  = (const float*)d_in[0];
    const void*  ei     = d_in[1];
    const float* ew     = (const float*)d_in[2];
    const float* W1     = (const float*)d_in[3];
    const float* b1     = (const float*)d_in[4];
    const float* W2     = (const float*)d_in[5];
    const float* b2     = (const float*)d_in[6];
    const float* W_ih   = (const float*)d_in[7];
    const float* W_hh   = (const float*)d_in[8];
    const float* b_ih   = (const float*)d_in[9];
    const float* b_hh   = (const float*)d_in[10];
    const float* dec_b  = (const float*)d_in[11];

    const int E = in_sizes[2];
    const int N = in_sizes[0] / (T_STEPS * IN_DIM);
    const int MT = T_STEPS * N;   // 120000 batched rows
    float* out = (float*)d_out;

    float *p_aggx, *p_h1, *p_zseq, *p_gi, *p_h;
    cudaGetSymbolAddress((void**)&p_aggx, g_aggx);
    cudaGetSymbolAddress((void**)&p_h1,   g_h1);
    cudaGetSymbolAddress((void**)&p_zseq, g_zseq);
    cudaGetSymbolAddress((void**)&p_gi,   g_gi);
    cudaGetSymbolAddress((void**)&p_h,    g_h);

    // --- preprocessing: degrees, norms, CSR by destination ---
    zero_pre_kernel<<<(N + 255) / 256, 256>>>(N);
    detect_kernel<<<(E + 255) / 256, 256>>>(ei, E, N);
    deg_kernel<<<(E + N + 255) / 256, 256>>>(ei, ew, E, N);
    dinv_kernel<<<(N + 255) / 256, 256>>>(N);
    scan_kernel<<<1, 1024>>>(N);
    scatter_kernel<<<(E + N + 255) / 256, 256>>>(ei, ew, E, N);

    const int aggBlocks = (N * 32 + 255) / 256;

    // --- encoder, batched over all T ---
    // aggx = S^T x   (layer-1 aggregation moved before W1: (S^T x) W1 == S^T (x W1))
    agg_kernel<<<aggBlocks, 256>>>(x_seq, p_aggx, nullptr, N);
    // H1 = relu(aggx @ W1 + b1)
    {
        dim3 g(1, (MT + 127) / 128);
        sgemm_kernel<<<g, 256>>>(p_aggx, W1, p_h1, MT, HID_DIM, IN_DIM, b1, 1, 0);
    }
    // P = H1 @ W2   (reuse aggx buffer)
    {
        dim3 g(1, (MT + 127) / 128);
        sgemm_kernel<<<g, 256>>>(p_h1, W2, p_aggx, MT, EMB_DIM, HID_DIM, nullptr, 0, 0);
    }
    // zseq = S^T P + b2
    agg_kernel<<<aggBlocks, 256>>>(p_aggx, p_zseq, b2, N);

    // --- GRU: hoisted input projection GI = zseq @ W_ih^T + b_ih ---
    {
        dim3 g(2, (MT + 127) / 128);
        sgemm_kernel<<<g, 256>>>(p_zseq, W_ih, p_gi, MT, 3 * EMB_DIM, EMB_DIM, b_ih, 2, 1);
    }
    zero_f_kernel<<<((long long)N * EMB_DIM + 255) / 256, 256>>>(p_h, (long long)N * EMB_DIM);
    for (int t = 0; t < T_STEPS; t++) {
        gru_kernel<<<(N + 3) / 4, 256>>>(p_gi + (size_t)t * N * 3 * EMB_DIM, W_hh, b_hh, p_h, N);
    }

    // --- decode: out = softplus(h @ h^T + dec_bias) ---
    {
        dim3 g((N + 127) / 128, (N + 127) / 128);
        sgemm_kernel<<<g, 256>>>(p_h, p_h, out, N, N, EMB_DIM, dec_b, 3, 1);
    }
    // append z (final hidden) if output buffer carries both tuple elements
    if ((long long)out_size >= (long long)N * N + (long long)N * EMB_DIM) {
        copy_z_kernel<<<(N * EMB_DIM + 255) / 256, 256>>>(out + (size_t)N * N, N * EMB_DIM);
    }
}

// round 2
// speedup vs baseline: 2.3252x; 2.3252x over previous
#include <cuda_runtime.h>
#include <math.h>
#include <stdint.h>

#define T_STEPS 12
#define IN_DIM  64
#define HID_DIM 128
#define EMB_DIM 64
#define NMAX    10000
#define EMAX    320000
#define ETOT    (EMAX + NMAX)
#define FULLM   0xffffffffu

// ---------------- scratch (device globals; no allocation allowed) ----------------
__device__ float g_deg[NMAX];
__device__ float g_dinv[NMAX];
__device__ int   g_cnt[NMAX];
__device__ int   g_fill[NMAX];
__device__ int   g_ptr[NMAX + 1];
__device__ int   g_src[ETOT];
__device__ float g_val[ETOT];
__device__ int   g_idx32;  // 1 if edge_index is int32, 0 if int64

__device__ float g_aggx[(size_t)T_STEPS * NMAX * IN_DIM];   // reused later as P
__device__ float g_h1  [(size_t)T_STEPS * NMAX * HID_DIM];
__device__ float g_zseq[(size_t)T_STEPS * NMAX * EMB_DIM];
__device__ float g_gi  [(size_t)T_STEPS * NMAX * 3 * EMB_DIM];
__device__ float g_h   [(size_t)NMAX * EMB_DIM];

// ---------------- f32x2 helpers ----------------
__device__ __forceinline__ unsigned long long dup2(float a) {
    unsigned long long r;
    asm("mov.b64 %0, {%1, %1};" : "=l"(r) : "f"(a));
    return r;
}
__device__ __forceinline__ void fma2(unsigned long long& acc, unsigned long long a, unsigned long long b) {
    asm("fma.rn.f32x2 %0, %1, %2, %0;" : "+l"(acc) : "l"(a), "l"(b));
}
__device__ __forceinline__ void unpack2(unsigned long long v, float& lo, float& hi) {
    asm("mov.b64 {%0, %1}, %2;" : "=f"(lo), "=f"(hi) : "l"(v));
}
__device__ __forceinline__ float sigm_fast(float x) {
    return 1.f / (1.f + __expf(-x));
}

// ---------------- helpers ----------------
__device__ __forceinline__ int load_idx(const void* ei, long long i) {
    if (g_idx32) return ((const int*)ei)[i];
    return (int)(((const long long*)ei)[i]);
}

// ---------------- preprocessing ----------------
__global__ void zero_pre_kernel(int N) {
    int i = blockIdx.x * blockDim.x + threadIdx.x;
    if (i < N) { g_deg[i] = 0.f; g_cnt[i] = 0; g_fill[i] = 0; }
    if (i == 0) g_idx32 = 0;
}

__global__ void detect_kernel(const void* ei, int E, int N) {
    int i = blockIdx.x * blockDim.x + threadIdx.x;
    if (i >= E) return;
    long long v = ((const long long*)ei)[i];
    if (v < 0 || v >= (long long)N) atomicOr(&g_idx32, 1);
}

__global__ void deg_kernel(const void* ei, const float* __restrict__ ew, int E, int N) {
    int i = blockIdx.x * blockDim.x + threadIdx.x;
    if (i < E) {
        int c = load_idx(ei, (long long)E + i);
        atomicAdd(&g_deg[c], ew[i]);
        atomicAdd(&g_cnt[c], 1);
    } else if (i < E + N) {
        int v = i - E;
        atomicAdd(&g_deg[v], 1.0f);
        atomicAdd(&g_cnt[v], 1);
    }
}

__global__ void dinv_kernel(int N) {
    int i = blockIdx.x * blockDim.x + threadIdx.x;
    if (i < N) {
        float d = g_deg[i];
        g_dinv[i] = (d > 0.f) ? rsqrtf(d) : 0.f;
    }
}

__global__ void scan_kernel(int n) {
    __shared__ int sh[1024];
    int tid = threadIdx.x;
    int carry = 0;
    for (int base = 0; base < n; base += 1024) {
        int v = (base + tid < n) ? g_cnt[base + tid] : 0;
        sh[tid] = v;
        __syncthreads();
        #pragma unroll
        for (int off = 1; off < 1024; off <<= 1) {
            int t = (tid >= off) ? sh[tid - off] : 0;
            __syncthreads();
            sh[tid] += t;
            __syncthreads();
        }
        if (base + tid < n) g_ptr[base + tid] = carry + sh[tid] - v;
        carry += sh[1023];
        __syncthreads();
    }
    if (tid == 0) g_ptr[n] = carry;
}

__global__ void scatter_kernel(const void* ei, const float* __restrict__ ew, int E, int N) {
    int i = blockIdx.x * blockDim.x + threadIdx.x;
    if (i < E) {
        int r = load_idx(ei, i);
        int c = load_idx(ei, (long long)E + i);
        int p = g_ptr[c] + atomicAdd(&g_fill[c], 1);
        g_src[p] = r;
        g_val[p] = g_dinv[r] * ew[i] * g_dinv[c];
    } else if (i < E + N) {
        int v = i - E;
        int p = g_ptr[v] + atomicAdd(&g_fill[v], 1);
        g_src[p] = v;
        g_val[p] = g_dinv[v] * g_dinv[v];
    }
}

// ---------------- batched (over T) 64-dim aggregation ----------------
__global__ void agg_kernel(const float* __restrict__ src, float* __restrict__ dst,
                           const float* __restrict__ bias, int N) {
    int warp = (blockIdx.x * blockDim.x + threadIdx.x) >> 5;
    int lane = threadIdx.x & 31;
    if (warp >= N) return;
    int e0 = g_ptr[warp], e1 = g_ptr[warp + 1];
    unsigned long long acc2[T_STEPS];
    #pragma unroll
    for (int t = 0; t < T_STEPS; t++) acc2[t] = 0ull;
    const int tstride2 = N * 32;  // u64 elems per timestep
    for (int e = e0; e < e1; e += 32) {
        int got = e1 - e; if (got > 32) got = 32;
        int r = 0; float v = 0.f;
        if (lane < got) { r = g_src[e + lane]; v = g_val[e + lane]; }
        for (int j = 0; j < got; j++) {
            int   rr = __shfl_sync(FULLM, r, j);
            float vv = __shfl_sync(FULLM, v, j);
            unsigned long long v2 = dup2(vv);
            const unsigned long long* xp =
                reinterpret_cast<const unsigned long long*>(src + (size_t)rr * 64) + lane;
            #pragma unroll
            for (int t = 0; t < T_STEPS; t++)
                fma2(acc2[t], v2, xp[t * tstride2]);
        }
    }
    float bx = 0.f, by = 0.f;
    if (bias) { bx = bias[2 * lane]; by = bias[2 * lane + 1]; }
    #pragma unroll
    for (int t = 0; t < T_STEPS; t++) {
        float lo, hi; unpack2(acc2[t], lo, hi);
        float2 o; o.x = lo + bx; o.y = hi + by;
        *reinterpret_cast<float2*>(dst + (size_t)t * N * 64 + (size_t)warp * 64 + 2 * lane) = o;
    }
}

// ---------------- generic SGEMM (f32x2 inner): C[M,N] = A[M,K] @ B + epilogue ----------------
// transB=0: B is [K,N] row-major. transB=1: B is [N,K] row-major.
// epi: 0 none, 1 bias+relu, 2 bias, 3 softplus(x + bias[0])
__global__ __launch_bounds__(256, 2) void sgemm_kernel(
    const float* __restrict__ A, const float* __restrict__ B, float* __restrict__ C,
    int M, int N, int K, const float* __restrict__ bias, int epi, int transB)
{
    __shared__ __align__(16) float As[8][128];
    __shared__ __align__(16) float Bs[8][128];
    const int tid = threadIdx.x;
    const int bm = blockIdx.y * 128;
    const int bn = blockIdx.x * 128;
    const int tr = (tid / 16) * 8;
    const int tc = (tid % 16) * 8;

    unsigned long long acc2[8][4];
    #pragma unroll
    for (int i = 0; i < 8; i++)
        #pragma unroll
        for (int j = 0; j < 4; j++) acc2[i][j] = 0ull;

    const int arow = tid >> 1;
    const int acol = (tid & 1) * 4;

    for (int kt = 0; kt < K; kt += 8) {
        float4 av = make_float4(0.f, 0.f, 0.f, 0.f);
        if (bm + arow < M)
            av = *reinterpret_cast<const float4*>(A + (size_t)(bm + arow) * K + kt + acol);
        As[acol + 0][arow] = av.x; As[acol + 1][arow] = av.y;
        As[acol + 2][arow] = av.z; As[acol + 3][arow] = av.w;

        if (!transB) {
            int kr = tid >> 5;
            int cc = (tid & 31) * 4;
            float4 bv = make_float4(0.f, 0.f, 0.f, 0.f);
            if (bn + cc < N)
                bv = *reinterpret_cast<const float4*>(B + (size_t)(kt + kr) * N + bn + cc);
            *reinterpret_cast<float4*>(&Bs[kr][cc]) = bv;
        } else {
            int cc = tid >> 1;
            int kk = (tid & 1) * 4;
            float4 bv = make_float4(0.f, 0.f, 0.f, 0.f);
            if (bn + cc < N)
                bv = *reinterpret_cast<const float4*>(B + (size_t)(bn + cc) * K + kt + kk);
            Bs[kk + 0][cc] = bv.x; Bs[kk + 1][cc] = bv.y;
            Bs[kk + 2][cc] = bv.z; Bs[kk + 3][cc] = bv.w;
        }
        __syncthreads();

        #pragma unroll
        for (int k = 0; k < 8; k++) {
            float ar[8];
            *reinterpret_cast<float4*>(ar)     = *reinterpret_cast<const float4*>(&As[k][tr]);
            *reinterpret_cast<float4*>(ar + 4) = *reinterpret_cast<const float4*>(&As[k][tr + 4]);
            ulonglong2 b0 = *reinterpret_cast<const ulonglong2*>(&Bs[k][tc]);
            ulonglong2 b1 = *reinterpret_cast<const ulonglong2*>(&Bs[k][tc + 4]);
            #pragma unroll
            for (int i = 0; i < 8; i++) {
                unsigned long long ad = dup2(ar[i]);
                fma2(acc2[i][0], ad, b0.x);
                fma2(acc2[i][1], ad, b0.y);
                fma2(acc2[i][2], ad, b1.x);
                fma2(acc2[i][3], ad, b1.y);
            }
        }
        __syncthreads();
    }

    float bsc = 0.f;
    if (epi == 3 && bias) bsc = bias[0];

    #pragma unroll
    for (int i = 0; i < 8; i++) {
        int r = bm + tr + i;
        if (r >= M) continue;
        float acc[8];
        #pragma unroll
        for (int jp = 0; jp < 4; jp++) unpack2(acc2[i][jp], acc[2 * jp], acc[2 * jp + 1]);
        #pragma unroll
        for (int jj = 0; jj < 8; jj += 4) {
            int c = bn + tc + jj;
            if (c >= N) continue;
            float4 v4;
            float* vp = reinterpret_cast<float*>(&v4);
            #pragma unroll
            for (int q = 0; q < 4; q++) {
                float v = acc[jj + q];
                if (epi == 1)      { v += bias[c + q]; v = fmaxf(v, 0.f); }
                else if (epi == 2) { v += bias[c + q]; }
                else if (epi == 3) {
                    v += bsc;
                    float e = __expf(-fabsf(v));
                    v = fmaxf(v, 0.f) + __logf(1.f + e);
                }
                vp[q] = v;
            }
            *reinterpret_cast<float4*>(C + (size_t)r * N + c) = v4;
        }
    }
}

// ---------------- fused GRU: all 12 steps in one launch ----------------
// warp per node; h kept in registers (2 per lane), broadcast via shfl;
// Whh in smem with XOR-rotation swizzle -> conflict-free float4 LDS.
__global__ __launch_bounds__(512) void gru_fused_kernel(
    const float* __restrict__ gi,    // [T][N][192] (includes b_ih)
    const float* __restrict__ Whh,   // [192][64]
    const float* __restrict__ bhh,   // [192]
    float* __restrict__ h, int N)
{
    __shared__ float ws[192 * 64];   // 48KB, swizzled: ws[r*64 + ((k+4r)&63)] = Whh[r][k]
    const int tid = threadIdx.x;
    for (int idx = tid; idx < 192 * 64; idx += 512) {
        int r = idx >> 6, k = idx & 63;
        ws[(r << 6) | ((k + 4 * r) & 63)] = Whh[idx];
    }
    __syncthreads();

    const int warp = tid >> 5, lane = tid & 31;
    const int node = blockIdx.x * 16 + warp;
    if (node >= N) return;
    const int c = lane, c2 = lane + 32;

    const float bRc = bhh[c],       bRd = bhh[c2];
    const float bZc = bhh[64 + c],  bZd = bhh[64 + c2];
    const float bNc = bhh[128 + c], bNd = bhh[128 + c2];

    float hA = 0.f, hB = 0.f;
    const float* gbase = gi + (size_t)node * 192;
    const long long gstep = (long long)N * 192;

    const int r1 = c, r2 = c2, r3 = 64 + c, r4 = 64 + c2, r5 = 128 + c, r6 = 128 + c2;

    #pragma unroll 1
    for (int t = 0; t < T_STEPS; t++) {
        float aRc = bRc, aRd = bRd, aZc = bZc, aZd = bZd, aNc = bNc, aNd = bNd;
        #pragma unroll
        for (int kc = 0; kc < 64; kc += 4) {
            float hv0, hv1, hv2, hv3;
            if (kc < 32) {
                hv0 = __shfl_sync(FULLM, hA, kc + 0);
                hv1 = __shfl_sync(FULLM, hA, kc + 1);
                hv2 = __shfl_sync(FULLM, hA, kc + 2);
                hv3 = __shfl_sync(FULLM, hA, kc + 3);
            } else {
                hv0 = __shfl_sync(FULLM, hB, kc - 32);
                hv1 = __shfl_sync(FULLM, hB, kc - 31);
                hv2 = __shfl_sync(FULLM, hB, kc - 30);
                hv3 = __shfl_sync(FULLM, hB, kc - 29);
            }
            float4 w1 = *reinterpret_cast<const float4*>(&ws[(r1 << 6) | ((kc + 4 * r1) & 63)]);
            float4 w2 = *reinterpret_cast<const float4*>(&ws[(r2 << 6) | ((kc + 4 * r2) & 63)]);
            float4 w3 = *reinterpret_cast<const float4*>(&ws[(r3 << 6) | ((kc + 4 * r3) & 63)]);
            float4 w4 = *reinterpret_cast<const float4*>(&ws[(r4 << 6) | ((kc + 4 * r4) & 63)]);
            float4 w5 = *reinterpret_cast<const float4*>(&ws[(r5 << 6) | ((kc + 4 * r5) & 63)]);
            float4 w6 = *reinterpret_cast<const float4*>(&ws[(r6 << 6) | ((kc + 4 * r6) & 63)]);
            aRc = fmaf(w1.x, hv0, aRc); aRc = fmaf(w1.y, hv1, aRc);
            aRc = fmaf(w1.z, hv2, aRc); aRc = fmaf(w1.w, hv3, aRc);
            aRd = fmaf(w2.x, hv0, aRd); aRd = fmaf(w2.y, hv1, aRd);
            aRd = fmaf(w2.z, hv2, aRd); aRd = fmaf(w2.w, hv3, aRd);
            aZc = fmaf(w3.x, hv0, aZc); aZc = fmaf(w3.y, hv1, aZc);
            aZc = fmaf(w3.z, hv2, aZc); aZc = fmaf(w3.w, hv3, aZc);
            aZd = fmaf(w4.x, hv0, aZd); aZd = fmaf(w4.y, hv1, aZd);
            aZd = fmaf(w4.z, hv2, aZd); aZd = fmaf(w4.w, hv3, aZd);
            aNc = fmaf(w5.x, hv0, aNc); aNc = fmaf(w5.y, hv1, aNc);
            aNc = fmaf(w5.z, hv2, aNc); aNc = fmaf(w5.w, hv3, aNc);
            aNd = fmaf(w6.x, hv0, aNd); aNd = fmaf(w6.y, hv1, aNd);
            aNd = fmaf(w6.z, hv2, aNd); aNd = fmaf(w6.w, hv3, aNd);
        }
        float g0 = gbase[c],       g1 = gbase[c2];
        float g2 = gbase[64 + c],  g3 = gbase[64 + c2];
        float g4 = gbase[128 + c], g5 = gbase[128 + c2];
        float rg1 = sigm_fast(g0 + aRc), rg2 = sigm_fast(g1 + aRd);
        float zg1 = sigm_fast(g2 + aZc), zg2 = sigm_fast(g3 + aZd);
        float n1 = tanhf(g4 + rg1 * aNc), n2 = tanhf(g5 + rg2 * aNd);
        hA = (1.f - zg1) * n1 + zg1 * hA;
        hB = (1.f - zg2) * n2 + zg2 * hB;
        gbase += gstep;
    }
    h[(size_t)node * 64 + c]  = hA;
    h[(size_t)node * 64 + c2] = hB;
}

__global__ void copy_z_kernel(float* __restrict__ out, int n) {
    int i = blockIdx.x * blockDim.x + threadIdx.x;
    if (i < n) out[i] = g_h[i];
}

// ---------------- launch ----------------
extern "C" void kernel_launch(void* const* d_in, const int* in_sizes, int n_in,
                              void* d_out, int out_size) {
    const float* x_seq  = (const float*)d_in[0];
    const void*  ei     = d_in[1];
    const float* ew     = (const float*)d_in[2];
    const float* W1     = (const float*)d_in[3];
    const float* b1     = (const float*)d_in[4];
    const float* W2     = (const float*)d_in[5];
    const float* b2     = (const float*)d_in[6];
    const float* W_ih   = (const float*)d_in[7];
    const float* W_hh   = (const float*)d_in[8];
    const float* b_ih   = (const float*)d_in[9];
    const float* b_hh   = (const float*)d_in[10];
    const float* dec_b  = (const float*)d_in[11];

    const int E = in_sizes[2];
    const int N = in_sizes[0] / (T_STEPS * IN_DIM);
    const int MT = T_STEPS * N;
    float* out = (float*)d_out;

    float *p_aggx, *p_h1, *p_zseq, *p_gi, *p_h;
    cudaGetSymbolAddress((void**)&p_aggx, g_aggx);
    cudaGetSymbolAddress((void**)&p_h1,   g_h1);
    cudaGetSymbolAddress((void**)&p_zseq, g_zseq);
    cudaGetSymbolAddress((void**)&p_gi,   g_gi);
    cudaGetSymbolAddress((void**)&p_h,    g_h);

    // --- preprocessing ---
    zero_pre_kernel<<<(N + 255) / 256, 256>>>(N);
    detect_kernel<<<(E + 255) / 256, 256>>>(ei, E, N);
    deg_kernel<<<(E + N + 255) / 256, 256>>>(ei, ew, E, N);
    dinv_kernel<<<(N + 255) / 256, 256>>>(N);
    scan_kernel<<<1, 1024>>>(N);
    scatter_kernel<<<(E + N + 255) / 256, 256>>>(ei, ew, E, N);

    const int aggBlocks = (N * 32 + 255) / 256;

    // --- encoder, batched over all T ---
    agg_kernel<<<aggBlocks, 256>>>(x_seq, p_aggx, nullptr, N);
    {
        dim3 g(1, (MT + 127) / 128);
        sgemm_kernel<<<g, 256>>>(p_aggx, W1, p_h1, MT, HID_DIM, IN_DIM, b1, 1, 0);
    }
    {
        dim3 g(1, (MT + 127) / 128);
        sgemm_kernel<<<g, 256>>>(p_h1, W2, p_aggx, MT, EMB_DIM, HID_DIM, nullptr, 0, 0);
    }
    agg_kernel<<<aggBlocks, 256>>>(p_aggx, p_zseq, b2, N);

    // --- GRU ---
    {
        dim3 g(2, (MT + 127) / 128);
        sgemm_kernel<<<g, 256>>>(p_zseq, W_ih, p_gi, MT, 3 * EMB_DIM, EMB_DIM, b_ih, 2, 1);
    }
    gru_fused_kernel<<<(N + 15) / 16, 512>>>(p_gi, W_hh, b_hh, p_h, N);

    // --- decode: out = softplus(h @ h^T + dec_bias) ---
    {
        dim3 g((N + 127) / 128, (N + 127) / 128);
        sgemm_kernel<<<g, 256>>>(p_h, p_h, out, N, N, EMB_DIM, dec_b, 3, 1);
    }
    if ((long long)out_size >= (long long)N * N + (long long)N * EMB_DIM) {
        copy_z_kernel<<<(N * EMB_DIM + 255) / 256, 256>>>(out + (size_t)N * N, N * EMB_DIM);
    }
}

// round 5
// speedup vs baseline: 2.4390x; 1.0489x over previous
#include <cuda_runtime.h>
#include <cuda_bf16.h>
#include <math.h>
#include <stdint.h>

#define T_STEPS 12
#define IN_DIM  64
#define HID_DIM 128
#define EMB_DIM 64
#define NMAX    10000
#define EMAX    320000
#define ETOT    (EMAX + NMAX)
#define FULLM   0xffffffffu

// ---------------- scratch (device globals; no allocation allowed) ----------------
__device__ float g_deg[NMAX];
__device__ float g_dinv[NMAX];
__device__ int   g_cnt[NMAX];
__device__ int   g_fill[NMAX];
__device__ int   g_ptr[NMAX + 1];
__device__ int   g_src[ETOT];
__device__ float g_val[ETOT];
__device__ int   g_idx32;

__device__ float g_aggx[(size_t)T_STEPS * NMAX * IN_DIM];
__device__ float g_h1  [(size_t)T_STEPS * NMAX * HID_DIM];
__device__ float g_zseq[(size_t)T_STEPS * NMAX * EMB_DIM];
__device__ float g_gi  [(size_t)T_STEPS * NMAX * 3 * EMB_DIM];
__device__ float g_h   [(size_t)NMAX * EMB_DIM];
__device__ uint16_t g_hh[(size_t)NMAX * EMB_DIM];   // bf16 hi part of h
__device__ uint16_t g_hl[(size_t)NMAX * EMB_DIM];   // bf16 lo part of h

// ---------------- f32x2 helpers ----------------
__device__ __forceinline__ unsigned long long dup2(float a) {
    unsigned long long r;
    asm("mov.b64 %0, {%1, %1};" : "=l"(r) : "f"(a));
    return r;
}
__device__ __forceinline__ void fma2(unsigned long long& acc, unsigned long long a, unsigned long long b) {
    asm("fma.rn.f32x2 %0, %1, %2, %0;" : "+l"(acc) : "l"(a), "l"(b));
}
__device__ __forceinline__ void unpack2(unsigned long long v, float& lo, float& hi) {
    asm("mov.b64 {%0, %1}, %2;" : "=f"(lo), "=f"(hi) : "l"(v));
}
__device__ __forceinline__ float sigm_fast(float x) { return 1.f / (1.f + __expf(-x)); }

__device__ __forceinline__ uint32_t smem_u32(const void* p) {
    uint32_t a;
    asm("{ .reg .u64 t; cvta.to.shared.u64 t, %1; cvt.u32.u64 %0, t; }" : "=r"(a) : "l"(p));
    return a;
}
#define SW128(o) ((o) ^ (((o) >> 3) & 0x70))

// ---------------- warp-level bf16 MMA helpers (generic sm_80+, OK on sm_103) -----
#define LDSM4(r0, r1, r2, r3, addr) \
    asm volatile("ldmatrix.sync.aligned.m8n8.x4.shared.b16 {%0,%1,%2,%3}, [%4];" \
        : "=r"(r0), "=r"(r1), "=r"(r2), "=r"(r3) : "r"(addr))
#define LDSM2(r0, r1, addr) \
    asm volatile("ldmatrix.sync.aligned.m8n8.x2.shared.b16 {%0,%1}, [%2];" \
        : "=r"(r0), "=r"(r1) : "r"(addr))

__device__ __forceinline__ void mma16816(float* c, const uint32_t* a, const uint32_t* b) {
    asm volatile("mma.sync.aligned.m16n8k16.row.col.f32.bf16.bf16.f32 "
        "{%0,%1,%2,%3}, {%4,%5,%6,%7}, {%8,%9}, {%0,%1,%2,%3};"
        : "+f"(c[0]), "+f"(c[1]), "+f"(c[2]), "+f"(c[3])
        : "r"(a[0]), "r"(a[1]), "r"(a[2]), "r"(a[3]), "r"(b[0]), "r"(b[1]));
}

// ---------------- helpers ----------------
__device__ __forceinline__ int load_idx(const void* ei, long long i) {
    if (g_idx32) return ((const int*)ei)[i];
    return (int)(((const long long*)ei)[i]);
}

// ---------------- preprocessing ----------------
__global__ void zero_pre_kernel(int N) {
    int i = blockIdx.x * blockDim.x + threadIdx.x;
    if (i < N) { g_deg[i] = 0.f; g_cnt[i] = 0; g_fill[i] = 0; }
    if (i == 0) g_idx32 = 0;
}

__global__ void detect_kernel(const void* ei, int E, int N) {
    int i = blockIdx.x * blockDim.x + threadIdx.x;
    if (i >= E) return;
    long long v = ((const long long*)ei)[i];
    if (v < 0 || v >= (long long)N) atomicOr(&g_idx32, 1);
}

__global__ void deg_kernel(const void* ei, const float* __restrict__ ew, int E, int N) {
    int i = blockIdx.x * blockDim.x + threadIdx.x;
    if (i < E) {
        int c = load_idx(ei, (long long)E + i);
        atomicAdd(&g_deg[c], ew[i]);
        atomicAdd(&g_cnt[c], 1);
    } else if (i < E + N) {
        int v = i - E;
        atomicAdd(&g_deg[v], 1.0f);
        atomicAdd(&g_cnt[v], 1);
    }
}

__global__ void dinv_kernel(int N) {
    int i = blockIdx.x * blockDim.x + threadIdx.x;
    if (i < N) {
        float d = g_deg[i];
        g_dinv[i] = (d > 0.f) ? rsqrtf(d) : 0.f;
    }
}

__global__ void scan_kernel(int n) {
    __shared__ int sh[1024];
    int tid = threadIdx.x;
    int carry = 0;
    for (int base = 0; base < n; base += 1024) {
        int v = (base + tid < n) ? g_cnt[base + tid] : 0;
        sh[tid] = v;
        __syncthreads();
        #pragma unroll
        for (int off = 1; off < 1024; off <<= 1) {
            int t = (tid >= off) ? sh[tid - off] : 0;
            __syncthreads();
            sh[tid] += t;
            __syncthreads();
        }
        if (base + tid < n) g_ptr[base + tid] = carry + sh[tid] - v;
        carry += sh[1023];
        __syncthreads();
    }
    if (tid == 0) g_ptr[n] = carry;
}

__global__ void scatter_kernel(const void* ei, const float* __restrict__ ew, int E, int N) {
    int i = blockIdx.x * blockDim.x + threadIdx.x;
    if (i < E) {
        int r = load_idx(ei, i);
        int c = load_idx(ei, (long long)E + i);
        int p = g_ptr[c] + atomicAdd(&g_fill[c], 1);
        g_src[p] = r;
        g_val[p] = g_dinv[r] * ew[i] * g_dinv[c];
    } else if (i < E + N) {
        int v = i - E;
        int p = g_ptr[v] + atomicAdd(&g_fill[v], 1);
        g_src[p] = v;
        g_val[p] = g_dinv[v] * g_dinv[v];
    }
}

// ---------------- batched (over T) 64-dim aggregation ----------------
__global__ void agg_kernel(const float* __restrict__ src, float* __restrict__ dst,
                           const float* __restrict__ bias, int N) {
    int warp = (blockIdx.x * blockDim.x + threadIdx.x) >> 5;
    int lane = threadIdx.x & 31;
    if (warp >= N) return;
    int e0 = g_ptr[warp], e1 = g_ptr[warp + 1];
    unsigned long long acc2[T_STEPS];
    #pragma unroll
    for (int t = 0; t < T_STEPS; t++) acc2[t] = 0ull;
    const int tstride2 = N * 32;
    for (int e = e0; e < e1; e += 32) {
        int got = e1 - e; if (got > 32) got = 32;
        int r = 0; float v = 0.f;
        if (lane < got) { r = g_src[e + lane]; v = g_val[e + lane]; }
        for (int j = 0; j < got; j++) {
            int   rr = __shfl_sync(FULLM, r, j);
            float vv = __shfl_sync(FULLM, v, j);
            unsigned long long v2 = dup2(vv);
            const unsigned long long* xp =
                reinterpret_cast<const unsigned long long*>(src + (size_t)rr * 64) + lane;
            #pragma unroll
            for (int t = 0; t < T_STEPS; t++)
                fma2(acc2[t], v2, xp[t * tstride2]);
        }
    }
    float bx = 0.f, by = 0.f;
    if (bias) { bx = bias[2 * lane]; by = bias[2 * lane + 1]; }
    #pragma unroll
    for (int t = 0; t < T_STEPS; t++) {
        float lo, hi; unpack2(acc2[t], lo, hi);
        float2 o; o.x = lo + bx; o.y = hi + by;
        *reinterpret_cast<float2*>(dst + (size_t)t * N * 64 + (size_t)warp * 64 + 2 * lane) = o;
    }
}

// ---------------- generic SGEMM (f32x2 inner) ----------------
__global__ __launch_bounds__(256, 2) void sgemm_kernel(
    const float* __restrict__ A, const float* __restrict__ B, float* __restrict__ C,
    int M, int N, int K, const float* __restrict__ bias, int epi, int transB)
{
    __shared__ __align__(16) float As[8][128];
    __shared__ __align__(16) float Bs[8][128];
    const int tid = threadIdx.x;
    const int bm = blockIdx.y * 128;
    const int bn = blockIdx.x * 128;
    const int tr = (tid / 16) * 8;
    const int tc = (tid % 16) * 8;

    unsigned long long acc2[8][4];
    #pragma unroll
    for (int i = 0; i < 8; i++)
        #pragma unroll
        for (int j = 0; j < 4; j++) acc2[i][j] = 0ull;

    const int arow = tid >> 1;
    const int acol = (tid & 1) * 4;

    for (int kt = 0; kt < K; kt += 8) {
        float4 av = make_float4(0.f, 0.f, 0.f, 0.f);
        if (bm + arow < M)
            av = *reinterpret_cast<const float4*>(A + (size_t)(bm + arow) * K + kt + acol);
        As[acol + 0][arow] = av.x; As[acol + 1][arow] = av.y;
        As[acol + 2][arow] = av.z; As[acol + 3][arow] = av.w;

        if (!transB) {
            int kr = tid >> 5;
            int cc = (tid & 31) * 4;
            float4 bv = make_float4(0.f, 0.f, 0.f, 0.f);
            if (bn + cc < N)
                bv = *reinterpret_cast<const float4*>(B + (size_t)(kt + kr) * N + bn + cc);
            *reinterpret_cast<float4*>(&Bs[kr][cc]) = bv;
        } else {
            int cc = tid >> 1;
            int kk = (tid & 1) * 4;
            float4 bv = make_float4(0.f, 0.f, 0.f, 0.f);
            if (bn + cc < N)
                bv = *reinterpret_cast<const float4*>(B + (size_t)(bn + cc) * K + kt + kk);
            Bs[kk + 0][cc] = bv.x; Bs[kk + 1][cc] = bv.y;
            Bs[kk + 2][cc] = bv.z; Bs[kk + 3][cc] = bv.w;
        }
        __syncthreads();

        #pragma unroll
        for (int k = 0; k < 8; k++) {
            float ar[8];
            *reinterpret_cast<float4*>(ar)     = *reinterpret_cast<const float4*>(&As[k][tr]);
            *reinterpret_cast<float4*>(ar + 4) = *reinterpret_cast<const float4*>(&As[k][tr + 4]);
            ulonglong2 b0 = *reinterpret_cast<const ulonglong2*>(&Bs[k][tc]);
            ulonglong2 b1 = *reinterpret_cast<const ulonglong2*>(&Bs[k][tc + 4]);
            #pragma unroll
            for (int i = 0; i < 8; i++) {
                unsigned long long ad = dup2(ar[i]);
                fma2(acc2[i][0], ad, b0.x);
                fma2(acc2[i][1], ad, b0.y);
                fma2(acc2[i][2], ad, b1.x);
                fma2(acc2[i][3], ad, b1.y);
            }
        }
        __syncthreads();
    }

    #pragma unroll
    for (int i = 0; i < 8; i++) {
        int r = bm + tr + i;
        if (r >= M) continue;
        float acc[8];
        #pragma unroll
        for (int jp = 0; jp < 4; jp++) unpack2(acc2[i][jp], acc[2 * jp], acc[2 * jp + 1]);
        #pragma unroll
        for (int jj = 0; jj < 8; jj += 4) {
            int c = bn + tc + jj;
            if (c >= N) continue;
            float4 v4;
            float* vp = reinterpret_cast<float*>(&v4);
            #pragma unroll
            for (int q = 0; q < 4; q++) {
                float v = acc[jj + q];
                if (epi == 1)      { v += bias[c + q]; v = fmaxf(v, 0.f); }
                else if (epi == 2) { v += bias[c + q]; }
                vp[q] = v;
            }
            *reinterpret_cast<float4*>(C + (size_t)r * N + c) = v4;
        }
    }
}

// ---------------- fused GRU ----------------
__global__ __launch_bounds__(512) void gru_fused_kernel(
    const float* __restrict__ gi, const float* __restrict__ Whh,
    const float* __restrict__ bhh, float* __restrict__ h, int N)
{
    __shared__ float ws[192 * 64];
    const int tid = threadIdx.x;
    for (int idx = tid; idx < 192 * 64; idx += 512) {
        int r = idx >> 6, k = idx & 63;
        ws[(r << 6) | ((k + 4 * r) & 63)] = Whh[idx];
    }
    __syncthreads();

    const int warp = tid >> 5, lane = tid & 31;
    const int node = blockIdx.x * 16 + warp;
    if (node >= N) return;
    const int c = lane, c2 = lane + 32;

    const float bRc = bhh[c],       bRd = bhh[c2];
    const float bZc = bhh[64 + c],  bZd = bhh[64 + c2];
    const float bNc = bhh[128 + c], bNd = bhh[128 + c2];

    float hA = 0.f, hB = 0.f;
    const float* gbase = gi + (size_t)node * 192;
    const long long gstep = (long long)N * 192;

    const int r1 = c, r2 = c2, r3 = 64 + c, r4 = 64 + c2, r5 = 128 + c, r6 = 128 + c2;

    #pragma unroll 1
    for (int t = 0; t < T_STEPS; t++) {
        float aRc = bRc, aRd = bRd, aZc = bZc, aZd = bZd, aNc = bNc, aNd = bNd;
        #pragma unroll
        for (int kc = 0; kc < 64; kc += 4) {
            float hv0, hv1, hv2, hv3;
            if (kc < 32) {
                hv0 = __shfl_sync(FULLM, hA, kc + 0);
                hv1 = __shfl_sync(FULLM, hA, kc + 1);
                hv2 = __shfl_sync(FULLM, hA, kc + 2);
                hv3 = __shfl_sync(FULLM, hA, kc + 3);
            } else {
                hv0 = __shfl_sync(FULLM, hB, kc - 32);
                hv1 = __shfl_sync(FULLM, hB, kc - 31);
                hv2 = __shfl_sync(FULLM, hB, kc - 30);
                hv3 = __shfl_sync(FULLM, hB, kc - 29);
            }
            float4 w1 = *reinterpret_cast<const float4*>(&ws[(r1 << 6) | ((kc + 4 * r1) & 63)]);
            float4 w2 = *reinterpret_cast<const float4*>(&ws[(r2 << 6) | ((kc + 4 * r2) & 63)]);
            float4 w3 = *reinterpret_cast<const float4*>(&ws[(r3 << 6) | ((kc + 4 * r3) & 63)]);
            float4 w4 = *reinterpret_cast<const float4*>(&ws[(r4 << 6) | ((kc + 4 * r4) & 63)]);
            float4 w5 = *reinterpret_cast<const float4*>(&ws[(r5 << 6) | ((kc + 4 * r5) & 63)]);
            float4 w6 = *reinterpret_cast<const float4*>(&ws[(r6 << 6) | ((kc + 4 * r6) & 63)]);
            aRc = fmaf(w1.x, hv0, aRc); aRc = fmaf(w1.y, hv1, aRc);
            aRc = fmaf(w1.z, hv2, aRc); aRc = fmaf(w1.w, hv3, aRc);
            aRd = fmaf(w2.x, hv0, aRd); aRd = fmaf(w2.y, hv1, aRd);
            aRd = fmaf(w2.z, hv2, aRd); aRd = fmaf(w2.w, hv3, aRd);
            aZc = fmaf(w3.x, hv0, aZc); aZc = fmaf(w3.y, hv1, aZc);
            aZc = fmaf(w3.z, hv2, aZc); aZc = fmaf(w3.w, hv3, aZc);
            aZd = fmaf(w4.x, hv0, aZd); aZd = fmaf(w4.y, hv1, aZd);
            aZd = fmaf(w4.z, hv2, aZd); aZd = fmaf(w4.w, hv3, aZd);
            aNc = fmaf(w5.x, hv0, aNc); aNc = fmaf(w5.y, hv1, aNc);
            aNc = fmaf(w5.z, hv2, aNc); aNc = fmaf(w5.w, hv3, aNc);
            aNd = fmaf(w6.x, hv0, aNd); aNd = fmaf(w6.y, hv1, aNd);
            aNd = fmaf(w6.z, hv2, aNd); aNd = fmaf(w6.w, hv3, aNd);
        }
        float g0 = gbase[c],       g1 = gbase[c2];
        float g2 = gbase[64 + c],  g3 = gbase[64 + c2];
        float g4 = gbase[128 + c], g5 = gbase[128 + c2];
        float rg1 = sigm_fast(g0 + aRc), rg2 = sigm_fast(g1 + aRd);
        float zg1 = sigm_fast(g2 + aZc), zg2 = sigm_fast(g3 + aZd);
        float n1 = tanhf(g4 + rg1 * aNc), n2 = tanhf(g5 + rg2 * aNd);
        hA = (1.f - zg1) * n1 + zg1 * hA;
        hB = (1.f - zg2) * n2 + zg2 * hB;
        gbase += gstep;
    }
    h[(size_t)node * 64 + c]  = hA;
    h[(size_t)node * 64 + c2] = hB;
}

// ---------------- bf16 split of h ----------------
__global__ void split_h_kernel(const float* __restrict__ h, int n) {
    int i = blockIdx.x * blockDim.x + threadIdx.x;
    if (i >= n) return;
    float v = h[i];
    __nv_bfloat16 bh = __float2bfloat16(v);
    float r = v - __bfloat162float(bh);
    g_hh[i] = __bfloat16_as_ushort(bh);
    g_hl[i] = __bfloat16_as_ushort(__float2bfloat16(r));
}

// ---------------- decode via warp-level bf16 mma: out = softplus(H H^T + b) ------
// 128x128 tile per CTA, 8 warps (warp tile 64x32), 3 bf16-split passes, K=64 each.
#define DSM_AHI 0
#define DSM_ALO 16384
#define DSM_BHI 32768
#define DSM_BLO 49152
#define DSM_TOTAL 65536

__global__ __launch_bounds__(256, 1) void decode_mma_kernel(
    const uint16_t* __restrict__ Hh, const uint16_t* __restrict__ Hl,
    float* __restrict__ out, int N, const float* __restrict__ dec_b)
{
    extern __shared__ __align__(1024) char smem[];
    const uint32_t sb = smem_u32(smem);
    const int tid = threadIdx.x;
    const int wid = tid >> 5, lane = tid & 31;
    const int bm = blockIdx.y * 128;
    const int bn = blockIdx.x * 128;

    // load 4 tiles: each 128 rows x 64 bf16 (128B rows), SW128-swizzled
    {
        const uint16_t* srcs[4]  = { Hh, Hl, Hh, Hl };
        const int       bases[4] = { bm, bm, bn, bn };
        const int       offs[4]  = { DSM_AHI, DSM_ALO, DSM_BHI, DSM_BLO };
        #pragma unroll
        for (int m = 0; m < 4; m++) {
            const uint16_t* s = srcs[m];
            int gb = bases[m], off = offs[m];
            for (int ck = tid; ck < 1024; ck += 256) {
                int row = ck >> 3, cc = ck & 7;
                uint4 v = make_uint4(0u, 0u, 0u, 0u);
                int gr = gb + row;
                if (gr < N) v = *reinterpret_cast<const uint4*>(s + (size_t)gr * 64 + cc * 8);
                int bo = row * 128 + cc * 16;
                *reinterpret_cast<uint4*>(smem + off + SW128(bo)) = v;
            }
        }
    }
    __syncthreads();

    const int mrow = (wid & 1) * 64;   // warp m-origin within tile
    const int ncol = (wid >> 1) * 32;  // warp n-origin within tile

    float acc[4][4][4];
    #pragma unroll
    for (int i = 0; i < 4; i++)
        #pragma unroll
        for (int j = 0; j < 4; j++)
            #pragma unroll
            for (int q = 0; q < 4; q++) acc[i][j][q] = 0.f;

    // lane-dependent ldmatrix row/khalf decomposition
    const int a_r   = mrow + (lane & 15);        // A: rows mrow..mrow+15 (+16*mf)
    const int a_kh  = (lane >> 4) * 16;          // bytes: k half select
    const int b_r   = ncol + (lane & 7);         // B: rows ncol..ncol+7 (+8*nf)
    const int b_kh  = ((lane >> 3) & 1) * 16;

    #pragma unroll
    for (int pass = 0; pass < 3; pass++) {
        const uint32_t aoff = sb + ((pass < 2) ? DSM_AHI : DSM_ALO);
        const uint32_t boff = sb + ((pass == 1) ? DSM_BLO : DSM_BHI);
        #pragma unroll
        for (int ks = 0; ks < 4; ks++) {
            const int kb = ks * 32;
            uint32_t a[4][4], b[4][2];
            #pragma unroll
            for (int mf = 0; mf < 4; mf++) {
                uint32_t addr = aoff + SW128((a_r + mf * 16) * 128 + kb + a_kh);
                LDSM4(a[mf][0], a[mf][1], a[mf][2], a[mf][3], addr);
            }
            #pragma unroll
            for (int nf = 0; nf < 4; nf++) {
                uint32_t addr = boff + SW128((b_r + nf * 8) * 128 + kb + b_kh);
                LDSM2(b[nf][0], b[nf][1], addr);
            }
            #pragma unroll
            for (int mf = 0; mf < 4; mf++)
                #pragma unroll
                for (int nf = 0; nf < 4; nf++)
                    mma16816(acc[mf][nf], a[mf], b[nf]);
        }
    }

    // epilogue: softplus + store; frag c0,c1 -> row lane/4; c2,c3 -> row+8
    const float bsc = dec_b[0];
    const int rr0 = bm + mrow + (lane >> 2);
    const int cc0 = bn + ncol + 2 * (lane & 3);
    #pragma unroll
    for (int mf = 0; mf < 4; mf++) {
        #pragma unroll
        for (int half = 0; half < 2; half++) {
            int row = rr0 + mf * 16 + half * 8;
            if (row >= N) continue;
            float* orow = out + (size_t)row * N;
            #pragma unroll
            for (int nf = 0; nf < 4; nf++) {
                int col = cc0 + nf * 8;
                if (col + 1 >= N && col >= N) continue;
                float v0 = acc[mf][nf][half * 2 + 0] + bsc;
                float v1 = acc[mf][nf][half * 2 + 1] + bsc;
                float e0 = __expf(-fabsf(v0)), e1 = __expf(-fabsf(v1));
                float2 o;
                o.x = fmaxf(v0, 0.f) + __logf(1.f + e0);
                o.y = fmaxf(v1, 0.f) + __logf(1.f + e1);
                if (col + 1 < N) {
                    *reinterpret_cast<float2*>(orow + col) = o;
                } else if (col < N) {
                    orow[col] = o.x;
                }
            }
        }
    }
}

__global__ void copy_z_kernel(float* __restrict__ out, int n) {
    int i = blockIdx.x * blockDim.x + threadIdx.x;
    if (i < n) out[i] = g_h[i];
}

// ---------------- launch ----------------
extern "C" void kernel_launch(void* const* d_in, const int* in_sizes, int n_in,
                              void* d_out, int out_size) {
    const float* x_seq  = (const float*)d_in[0];
    const void*  ei     = d_in[1];
    const float* ew     = (const float*)d_in[2];
    const float* W1     = (const float*)d_in[3];
    const float* b1     = (const float*)d_in[4];
    const float* W2     = (const float*)d_in[5];
    const float* b2     = (const float*)d_in[6];
    const float* W_ih   = (const float*)d_in[7];
    const float* W_hh   = (const float*)d_in[8];
    const float* b_ih   = (const float*)d_in[9];
    const float* b_hh   = (const float*)d_in[10];
    const float* dec_b  = (const float*)d_in[11];

    const int E = in_sizes[2];
    const int N = in_sizes[0] / (T_STEPS * IN_DIM);
    const int MT = T_STEPS * N;
    float* out = (float*)d_out;

    float *p_aggx, *p_h1, *p_zseq, *p_gi, *p_h;
    uint16_t *p_hh, *p_hl;
    cudaGetSymbolAddress((void**)&p_aggx, g_aggx);
    cudaGetSymbolAddress((void**)&p_h1,   g_h1);
    cudaGetSymbolAddress((void**)&p_zseq, g_zseq);
    cudaGetSymbolAddress((void**)&p_gi,   g_gi);
    cudaGetSymbolAddress((void**)&p_h,    g_h);
    cudaGetSymbolAddress((void**)&p_hh,   g_hh);
    cudaGetSymbolAddress((void**)&p_hl,   g_hl);

    cudaFuncSetAttribute(decode_mma_kernel, cudaFuncAttributeMaxDynamicSharedMemorySize, DSM_TOTAL);

    // --- preprocessing ---
    zero_pre_kernel<<<(N + 255) / 256, 256>>>(N);
    detect_kernel<<<(E + 255) / 256, 256>>>(ei, E, N);
    deg_kernel<<<(E + N + 255) / 256, 256>>>(ei, ew, E, N);
    dinv_kernel<<<(N + 255) / 256, 256>>>(N);
    scan_kernel<<<1, 1024>>>(N);
    scatter_kernel<<<(E + N + 255) / 256, 256>>>(ei, ew, E, N);

    const int aggBlocks = (N * 32 + 255) / 256;

    // --- encoder, batched over all T ---
    agg_kernel<<<aggBlocks, 256>>>(x_seq, p_aggx, nullptr, N);
    {
        dim3 g(1, (MT + 127) / 128);
        sgemm_kernel<<<g, 256>>>(p_aggx, W1, p_h1, MT, HID_DIM, IN_DIM, b1, 1, 0);
    }
    {
        dim3 g(1, (MT + 127) / 128);
        sgemm_kernel<<<g, 256>>>(p_h1, W2, p_aggx, MT, EMB_DIM, HID_DIM, nullptr, 0, 0);
    }
    agg_kernel<<<aggBlocks, 256>>>(p_aggx, p_zseq, b2, N);

    // --- GRU ---
    {
        dim3 g(2, (MT + 127) / 128);
        sgemm_kernel<<<g, 256>>>(p_zseq, W_ih, p_gi, MT, 3 * EMB_DIM, EMB_DIM, b_ih, 2, 1);
    }
    gru_fused_kernel<<<(N + 15) / 16, 512>>>(p_gi, W_hh, b_hh, p_h, N);

    // --- decode via warp-mma bf16-split ---
    split_h_kernel<<<(N * EMB_DIM + 255) / 256, 256>>>(p_h, N * EMB_DIM);
    {
        dim3 g((N + 127) / 128, (N + 127) / 128);
        decode_mma_kernel<<<g, 256, DSM_TOTAL>>>(p_hh, p_hl, out, N, dec_b);
    }
    if ((long long)out_size >= (long long)N * N + (long long)N * EMB_DIM) {
        copy_z_kernel<<<(N * EMB_DIM + 255) / 256, 256>>>(out + (size_t)N * N, N * EMB_DIM);
    }
}

// round 8
// speedup vs baseline: 2.7237x; 1.1167x over previous
#include <cuda_runtime.h>
#include <cuda_bf16.h>
#include <math.h>
#include <stdint.h>

#define T_STEPS 12
#define IN_DIM  64
#define HID_DIM 128
#define EMB_DIM 64
#define NMAX    10000
#define EMAX    320000
#define ETOT    (EMAX + NMAX)
#define FULLM   0xffffffffu

// ---------------- scratch (device globals; no allocation allowed) ----------------
__device__ float g_deg[NMAX];
__device__ float g_dinv[NMAX];
__device__ int   g_cnt[NMAX];
__device__ int   g_fill[NMAX];
__device__ int   g_ptr[NMAX + 1];
__device__ int   g_src[ETOT];
__device__ float g_val[ETOT];
__device__ int   g_idx32;

__device__ float g_aggx[(size_t)T_STEPS * NMAX * IN_DIM];
__device__ float g_h1  [(size_t)T_STEPS * NMAX * HID_DIM];
__device__ float g_zseq[(size_t)T_STEPS * NMAX * EMB_DIM];
__device__ float g_gi  [(size_t)T_STEPS * NMAX * 3 * EMB_DIM];
__device__ float g_h   [(size_t)NMAX * EMB_DIM];
__device__ uint16_t g_hh[(size_t)NMAX * EMB_DIM];   // bf16 hi part of h
__device__ uint16_t g_hl[(size_t)NMAX * EMB_DIM];   // bf16 lo part of h

// ---------------- f32x2 helpers ----------------
__device__ __forceinline__ unsigned long long dup2(float a) {
    unsigned long long r;
    asm("mov.b64 %0, {%1, %1};" : "=l"(r) : "f"(a));
    return r;
}
__device__ __forceinline__ unsigned long long pack2(float lo, float hi) {
    unsigned long long r;
    asm("mov.b64 %0, {%1, %2};" : "=l"(r) : "f"(lo), "f"(hi));
    return r;
}
__device__ __forceinline__ void fma2(unsigned long long& acc, unsigned long long a, unsigned long long b) {
    asm("fma.rn.f32x2 %0, %1, %2, %0;" : "+l"(acc) : "l"(a), "l"(b));
}
__device__ __forceinline__ void unpack2(unsigned long long v, float& lo, float& hi) {
    asm("mov.b64 {%0, %1}, %2;" : "=f"(lo), "=f"(hi) : "l"(v));
}
__device__ __forceinline__ float sigm_fast(float x) { return 1.f / (1.f + __expf(-x)); }

__device__ __forceinline__ uint32_t smem_u32(const void* p) {
    uint32_t a;
    asm("{ .reg .u64 t; cvta.to.shared.u64 t, %1; cvt.u32.u64 %0, t; }" : "=r"(a) : "l"(p));
    return a;
}
#define SW128(o) ((o) ^ (((o) >> 3) & 0x70))

// ---------------- warp-level bf16 MMA helpers (generic sm_80+, OK on sm_103) -----
#define LDSM4(r0, r1, r2, r3, addr) \
    asm volatile("ldmatrix.sync.aligned.m8n8.x4.shared.b16 {%0,%1,%2,%3}, [%4];" \
        : "=r"(r0), "=r"(r1), "=r"(r2), "=r"(r3) : "r"(addr))
#define LDSM2(r0, r1, addr) \
    asm volatile("ldmatrix.sync.aligned.m8n8.x2.shared.b16 {%0,%1}, [%2];" \
        : "=r"(r0), "=r"(r1) : "r"(addr))

__device__ __forceinline__ void mma16816(float* c, const uint32_t* a, const uint32_t* b) {
    asm volatile("mma.sync.aligned.m16n8k16.row.col.f32.bf16.bf16.f32 "
        "{%0,%1,%2,%3}, {%4,%5,%6,%7}, {%8,%9}, {%0,%1,%2,%3};"
        : "+f"(c[0]), "+f"(c[1]), "+f"(c[2]), "+f"(c[3])
        : "r"(a[0]), "r"(a[1]), "r"(a[2]), "r"(a[3]), "r"(b[0]), "r"(b[1]));
}

// ---------------- helpers ----------------
__device__ __forceinline__ int load_idx(const void* ei, long long i) {
    if (g_idx32) return ((const int*)ei)[i];
    return (int)(((const long long*)ei)[i]);
}

// ---------------- preprocessing ----------------
__global__ void zero_pre_kernel(int N) {
    int i = blockIdx.x * blockDim.x + threadIdx.x;
    if (i < N) { g_deg[i] = 0.f; g_cnt[i] = 0; g_fill[i] = 0; }
    if (i == 0) g_idx32 = 0;
}

// warp-aggregated detection: at most one atomic per warp
__global__ void detect_kernel(const void* ei, int E, int N) {
    int i = blockIdx.x * blockDim.x + threadIdx.x;
    bool bad = false;
    if (i < E) {
        long long v = ((const long long*)ei)[i];
        bad = (v < 0 || v >= (long long)N);
    }
    if (__any_sync(FULLM, bad)) {
        if ((threadIdx.x & 31) == 0) atomicOr(&g_idx32, 1);
    }
}

__global__ void deg_kernel(const void* ei, const float* __restrict__ ew, int E, int N) {
    int i = blockIdx.x * blockDim.x + threadIdx.x;
    if (i < E) {
        int c = load_idx(ei, (long long)E + i);
        atomicAdd(&g_deg[c], ew[i]);
        atomicAdd(&g_cnt[c], 1);
    } else if (i < E + N) {
        int v = i - E;
        atomicAdd(&g_deg[v], 1.0f);
        atomicAdd(&g_cnt[v], 1);
    }
}

__global__ void dinv_kernel(int N) {
    int i = blockIdx.x * blockDim.x + threadIdx.x;
    if (i < N) {
        float d = g_deg[i];
        g_dinv[i] = (d > 0.f) ? rsqrtf(d) : 0.f;
    }
}

// shfl-based exclusive scan: g_cnt -> g_ptr (single block, 1024 threads)
__global__ void scan_kernel(int n) {
    __shared__ int wsum[32];
    const int tid = threadIdx.x, lane = tid & 31, w = tid >> 5;
    int carry = 0;
    for (int base = 0; base < n; base += 1024) {
        int v = (base + tid < n) ? g_cnt[base + tid] : 0;
        int x = v;
        #pragma unroll
        for (int off = 1; off < 32; off <<= 1) {
            int t = __shfl_up_sync(FULLM, x, off);
            if (lane >= off) x += t;
        }
        if (lane == 31) wsum[w] = x;
        __syncthreads();
        if (w == 0) {
            int s = wsum[lane];
            #pragma unroll
            for (int off = 1; off < 32; off <<= 1) {
                int t = __shfl_up_sync(FULLM, s, off);
                if (lane >= off) s += t;
            }
            wsum[lane] = s;
        }
        __syncthreads();
        int woff = (w > 0) ? wsum[w - 1] : 0;
        if (base + tid < n) g_ptr[base + tid] = carry + woff + x - v;
        int tot = wsum[31];
        __syncthreads();
        carry += tot;
    }
    if (tid == 0) g_ptr[n] = carry;
}

__global__ void scatter_kernel(const void* ei, const float* __restrict__ ew, int E, int N) {
    int i = blockIdx.x * blockDim.x + threadIdx.x;
    if (i < E) {
        int r = load_idx(ei, i);
        int c = load_idx(ei, (long long)E + i);
        int p = g_ptr[c] + atomicAdd(&g_fill[c], 1);
        g_src[p] = r;
        g_val[p] = g_dinv[r] * ew[i] * g_dinv[c];
    } else if (i < E + N) {
        int v = i - E;
        int p = g_ptr[v] + atomicAdd(&g_fill[v], 1);
        g_src[p] = v;
        g_val[p] = g_dinv[v] * g_dinv[v];
    }
}

// ---------------- batched (over T) 64-dim aggregation ----------------
__global__ void agg_kernel(const float* __restrict__ src, float* __restrict__ dst,
                           const float* __restrict__ bias, int N) {
    int warp = (blockIdx.x * blockDim.x + threadIdx.x) >> 5;
    int lane = threadIdx.x & 31;
    if (warp >= N) return;
    int e0 = g_ptr[warp], e1 = g_ptr[warp + 1];
    unsigned long long acc2[T_STEPS];
    #pragma unroll
    for (int t = 0; t < T_STEPS; t++) acc2[t] = 0ull;
    const int tstride2 = N * 32;
    for (int e = e0; e < e1; e += 32) {
        int got = e1 - e; if (got > 32) got = 32;
        int r = 0; float v = 0.f;
        if (lane < got) { r = g_src[e + lane]; v = g_val[e + lane]; }
        for (int j = 0; j < got; j++) {
            int   rr = __shfl_sync(FULLM, r, j);
            float vv = __shfl_sync(FULLM, v, j);
            unsigned long long v2 = dup2(vv);
            const unsigned long long* xp =
                reinterpret_cast<const unsigned long long*>(src + (size_t)rr * 64) + lane;
            #pragma unroll
            for (int t = 0; t < T_STEPS; t++)
                fma2(acc2[t], v2, xp[t * tstride2]);
        }
    }
    float bx = 0.f, by = 0.f;
    if (bias) { bx = bias[2 * lane]; by = bias[2 * lane + 1]; }
    #pragma unroll
    for (int t = 0; t < T_STEPS; t++) {
        float lo, hi; unpack2(acc2[t], lo, hi);
        float2 o; o.x = lo + bx; o.y = hi + by;
        *reinterpret_cast<float2*>(dst + (size_t)t * N * 64 + (size_t)warp * 64 + 2 * lane) = o;
    }
}

// ---------------- generic SGEMM (f32x2 inner) ----------------
__global__ __launch_bounds__(256, 2) void sgemm_kernel(
    const float* __restrict__ A, const float* __restrict__ B, float* __restrict__ C,
    int M, int N, int K, const float* __restrict__ bias, int epi, int transB)
{
    __shared__ __align__(16) float As[8][128];
    __shared__ __align__(16) float Bs[8][128];
    const int tid = threadIdx.x;
    const int bm = blockIdx.y * 128;
    const int bn = blockIdx.x * 128;
    const int tr = (tid / 16) * 8;
    const int tc = (tid % 16) * 8;

    unsigned long long acc2[8][4];
    #pragma unroll
    for (int i = 0; i < 8; i++)
        #pragma unroll
        for (int j = 0; j < 4; j++) acc2[i][j] = 0ull;

    const int arow = tid >> 1;
    const int acol = (tid & 1) * 4;

    for (int kt = 0; kt < K; kt += 8) {
        float4 av = make_float4(0.f, 0.f, 0.f, 0.f);
        if (bm + arow < M)
            av = *reinterpret_cast<const float4*>(A + (size_t)(bm + arow) * K + kt + acol);
        As[acol + 0][arow] = av.x; As[acol + 1][arow] = av.y;
        As[acol + 2][arow] = av.z; As[acol + 3][arow] = av.w;

        if (!transB) {
            int kr = tid >> 5;
            int cc = (tid & 31) * 4;
            float4 bv = make_float4(0.f, 0.f, 0.f, 0.f);
            if (bn + cc < N)
                bv = *reinterpret_cast<const float4*>(B + (size_t)(kt + kr) * N + bn + cc);
            *reinterpret_cast<float4*>(&Bs[kr][cc]) = bv;
        } else {
            int cc = tid >> 1;
            int kk = (tid & 1) * 4;
            float4 bv = make_float4(0.f, 0.f, 0.f, 0.f);
            if (bn + cc < N)
                bv = *reinterpret_cast<const float4*>(B + (size_t)(bn + cc) * K + kt + kk);
            Bs[kk + 0][cc] = bv.x; Bs[kk + 1][cc] = bv.y;
            Bs[kk + 2][cc] = bv.z; Bs[kk + 3][cc] = bv.w;
        }
        __syncthreads();

        #pragma unroll
        for (int k = 0; k < 8; k++) {
            float ar[8];
            *reinterpret_cast<float4*>(ar)     = *reinterpret_cast<const float4*>(&As[k][tr]);
            *reinterpret_cast<float4*>(ar + 4) = *reinterpret_cast<const float4*>(&As[k][tr + 4]);
            ulonglong2 b0 = *reinterpret_cast<const ulonglong2*>(&Bs[k][tc]);
            ulonglong2 b1 = *reinterpret_cast<const ulonglong2*>(&Bs[k][tc + 4]);
            #pragma unroll
            for (int i = 0; i < 8; i++) {
                unsigned long long ad = dup2(ar[i]);
                fma2(acc2[i][0], ad, b0.x);
                fma2(acc2[i][1], ad, b0.y);
                fma2(acc2[i][2], ad, b1.x);
                fma2(acc2[i][3], ad, b1.y);
            }
        }
        __syncthreads();
    }

    #pragma unroll
    for (int i = 0; i < 8; i++) {
        int r = bm + tr + i;
        if (r >= M) continue;
        float acc[8];
        #pragma unroll
        for (int jp = 0; jp < 4; jp++) unpack2(acc2[i][jp], acc[2 * jp], acc[2 * jp + 1]);
        #pragma unroll
        for (int jj = 0; jj < 8; jj += 4) {
            int c = bn + tc + jj;
            if (c >= N) continue;
            float4 v4;
            float* vp = reinterpret_cast<float*>(&v4);
            #pragma unroll
            for (int q = 0; q < 4; q++) {
                float v = acc[jj + q];
                if (epi == 1)      { v += bias[c + q]; v = fmaxf(v, 0.f); }
                else if (epi == 2) { v += bias[c + q]; }
                vp[q] = v;
            }
            *reinterpret_cast<float4*>(C + (size_t)r * N + c) = v4;
        }
    }
}

// ---------------- fused GRU: 4 nodes/warp, f32x2 channel pairing ----------------
// Interleaved weight layout: ws4[(g*32 + k2)*32 + lane] =
//   float4( W[g*64+lane][2k2], W[g*64+32+lane][2k2], W[g*64+lane][2k2+1], W[g*64+32+lane][2k2+1] )
// Lane owns channels (lane, lane+32); weights loaded once per k serve 4 nodes.
__global__ __launch_bounds__(256) void gru_fused_kernel(
    const float* __restrict__ gi, const float* __restrict__ Whh,
    const float* __restrict__ bhh, float* __restrict__ h, int N)
{
    __shared__ __align__(16) float4 ws4[3 * 32 * 32];   // 48KB
    const int tid = threadIdx.x;
    for (int idx = tid; idx < 3 * 32 * 32; idx += 256) {
        int lane_ = idx & 31;
        int k2 = (idx >> 5) & 31;
        int g = idx >> 10;
        float4 f;
        f.x = Whh[(size_t)(g * 64 + lane_) * 64 + 2 * k2];
        f.y = Whh[(size_t)(g * 64 + 32 + lane_) * 64 + 2 * k2];
        f.z = Whh[(size_t)(g * 64 + lane_) * 64 + 2 * k2 + 1];
        f.w = Whh[(size_t)(g * 64 + 32 + lane_) * 64 + 2 * k2 + 1];
        ws4[idx] = f;
    }
    __syncthreads();

    const int warp = tid >> 5, lane = tid & 31;
    const int node0 = (blockIdx.x * 8 + warp) * 4;
    if (node0 >= N) return;

    const unsigned long long bR = pack2(bhh[lane],       bhh[32 + lane]);
    const unsigned long long bZ = pack2(bhh[64 + lane],  bhh[96 + lane]);
    const unsigned long long bN = pack2(bhh[128 + lane], bhh[160 + lane]);

    float hA[4] = {0.f, 0.f, 0.f, 0.f}, hB[4] = {0.f, 0.f, 0.f, 0.f};

    const float4* wR = ws4;
    const float4* wZ = ws4 + 32 * 32;
    const float4* wN = ws4 + 2 * 32 * 32;

    #pragma unroll 1
    for (int t = 0; t < T_STEPS; t++) {
        // prefetch gi for all 4 nodes (6 scalars per lane per node)
        float2 giR[4], giZ[4], giN[4];
        #pragma unroll
        for (int j = 0; j < 4; j++) {
            int node = node0 + j;
            if (node < N) {
                const float* gr = gi + ((size_t)t * N + node) * 192;
                giR[j] = make_float2(gr[lane],       gr[32 + lane]);
                giZ[j] = make_float2(gr[64 + lane],  gr[96 + lane]);
                giN[j] = make_float2(gr[128 + lane], gr[160 + lane]);
            } else {
                giR[j] = giZ[j] = giN[j] = make_float2(0.f, 0.f);
            }
        }

        unsigned long long aR[4], aZ[4], aN[4];
        #pragma unroll
        for (int j = 0; j < 4; j++) { aR[j] = bR; aZ[j] = bZ; aN[j] = bN; }

        if (t > 0) {
            #pragma unroll
            for (int k2 = 0; k2 < 32; k2++) {
                float4 r4 = wR[k2 * 32 + lane];
                float4 z4 = wZ[k2 * 32 + lane];
                float4 n4 = wN[k2 * 32 + lane];
                unsigned long long r0 = pack2(r4.x, r4.y), r1 = pack2(r4.z, r4.w);
                unsigned long long z0 = pack2(z4.x, z4.y), z1 = pack2(z4.z, z4.w);
                unsigned long long n0 = pack2(n4.x, n4.y), n1 = pack2(n4.z, n4.w);
                #pragma unroll
                for (int j = 0; j < 4; j++) {
                    float h0, h1;
                    if (k2 < 16) {
                        h0 = __shfl_sync(FULLM, hA[j], 2 * k2);
                        h1 = __shfl_sync(FULLM, hA[j], 2 * k2 + 1);
                    } else {
                        h0 = __shfl_sync(FULLM, hB[j], 2 * k2 - 32);
                        h1 = __shfl_sync(FULLM, hB[j], 2 * k2 - 31);
                    }
                    unsigned long long d0 = dup2(h0), d1 = dup2(h1);
                    fma2(aR[j], d0, r0); fma2(aR[j], d1, r1);
                    fma2(aZ[j], d0, z0); fma2(aZ[j], d1, z1);
                    fma2(aN[j], d0, n0); fma2(aN[j], d1, n1);
                }
            }
        }

        #pragma unroll
        for (int j = 0; j < 4; j++) {
            float aRlo, aRhi, aZlo, aZhi, aNlo, aNhi;
            unpack2(aR[j], aRlo, aRhi);
            unpack2(aZ[j], aZlo, aZhi);
            unpack2(aN[j], aNlo, aNhi);
            float rg1 = sigm_fast(giR[j].x + aRlo), rg2 = sigm_fast(giR[j].y + aRhi);
            float zg1 = sigm_fast(giZ[j].x + aZlo), zg2 = sigm_fast(giZ[j].y + aZhi);
            float n1 = tanhf(giN[j].x + rg1 * aNlo), n2 = tanhf(giN[j].y + rg2 * aNhi);
            hA[j] = (1.f - zg1) * n1 + zg1 * hA[j];
            hB[j] = (1.f - zg2) * n2 + zg2 * hB[j];
        }
    }

    #pragma unroll
    for (int j = 0; j < 4; j++) {
        int node = node0 + j;
        if (node < N) {
            h[(size_t)node * 64 + lane]      = hA[j];
            h[(size_t)node * 64 + 32 + lane] = hB[j];
        }
    }
}

// ---------------- bf16 split of h ----------------
__global__ void split_h_kernel(const float* __restrict__ h, int n) {
    int i = blockIdx.x * blockDim.x + threadIdx.x;
    if (i >= n) return;
    float v = h[i];
    __nv_bfloat16 bh = __float2bfloat16(v);
    float r = v - __bfloat162float(bh);
    g_hh[i] = __bfloat16_as_ushort(bh);
    g_hl[i] = __bfloat16_as_ushort(__float2bfloat16(r));
}

// ---------------- decode via warp-level bf16 mma: out = softplus(H H^T + b) ------
#define DSM_AHI 0
#define DSM_ALO 16384
#define DSM_BHI 32768
#define DSM_BLO 49152
#define DSM_TOTAL 65536

__global__ __launch_bounds__(256, 1) void decode_mma_kernel(
    const uint16_t* __restrict__ Hh, const uint16_t* __restrict__ Hl,
    float* __restrict__ out, int N, const float* __restrict__ dec_b)
{
    extern __shared__ __align__(1024) char smem[];
    const uint32_t sb = smem_u32(smem);
    const int tid = threadIdx.x;
    const int wid = tid >> 5, lane = tid & 31;
    const int bm = blockIdx.y * 128;
    const int bn = blockIdx.x * 128;

    {
        const uint16_t* srcs[4]  = { Hh, Hl, Hh, Hl };
        const int       bases[4] = { bm, bm, bn, bn };
        const int       offs[4]  = { DSM_AHI, DSM_ALO, DSM_BHI, DSM_BLO };
        #pragma unroll
        for (int m = 0; m < 4; m++) {
            const uint16_t* s = srcs[m];
            int gb = bases[m], off = offs[m];
            for (int ck = tid; ck < 1024; ck += 256) {
                int row = ck >> 3, cc = ck & 7;
                uint4 v = make_uint4(0u, 0u, 0u, 0u);
                int gr = gb + row;
                if (gr < N) v = *reinterpret_cast<const uint4*>(s + (size_t)gr * 64 + cc * 8);
                int bo = row * 128 + cc * 16;
                *reinterpret_cast<uint4*>(smem + off + SW128(bo)) = v;
            }
        }
    }
    __syncthreads();

    const int mrow = (wid & 1) * 64;
    const int ncol = (wid >> 1) * 32;

    float acc[4][4][4];
    #pragma unroll
    for (int i = 0; i < 4; i++)
        #pragma unroll
        for (int j = 0; j < 4; j++)
            #pragma unroll
            for (int q = 0; q < 4; q++) acc[i][j][q] = 0.f;

    const int a_r  = mrow + (lane & 15);
    const int a_kh = (lane >> 4) * 16;
    const int b_r  = ncol + (lane & 7);
    const int b_kh = ((lane >> 3) & 1) * 16;

    #pragma unroll
    for (int pass = 0; pass < 3; pass++) {
        const uint32_t aoff = sb + ((pass < 2) ? DSM_AHI : DSM_ALO);
        const uint32_t boff = sb + ((pass == 1) ? DSM_BLO : DSM_BHI);
        #pragma unroll
        for (int ks = 0; ks < 4; ks++) {
            const int kb = ks * 32;
            uint32_t a[4][4], b[4][2];
            #pragma unroll
            for (int mf = 0; mf < 4; mf++) {
                uint32_t addr = aoff + SW128((a_r + mf * 16) * 128 + kb + a_kh);
                LDSM4(a[mf][0], a[mf][1], a[mf][2], a[mf][3], addr);
            }
            #pragma unroll
            for (int nf = 0; nf < 4; nf++) {
                uint32_t addr = boff + SW128((b_r + nf * 8) * 128 + kb + b_kh);
                LDSM2(b[nf][0], b[nf][1], addr);
            }
            #pragma unroll
            for (int mf = 0; mf < 4; mf++)
                #pragma unroll
                for (int nf = 0; nf < 4; nf++)
                    mma16816(acc[mf][nf], a[mf], b[nf]);
        }
    }

    const float bsc = dec_b[0];
    const int rr0 = bm + mrow + (lane >> 2);
    const int cc0 = bn + ncol + 2 * (lane & 3);
    #pragma unroll
    for (int mf = 0; mf < 4; mf++) {
        #pragma unroll
        for (int half = 0; half < 2; half++) {
            int row = rr0 + mf * 16 + half * 8;
            if (row >= N) continue;
            float* orow = out + (size_t)row * N;
            #pragma unroll
            for (int nf = 0; nf < 4; nf++) {
                int col = cc0 + nf * 8;
                if (col + 1 >= N && col >= N) continue;
                float v0 = acc[mf][nf][half * 2 + 0] + bsc;
                float v1 = acc[mf][nf][half * 2 + 1] + bsc;
                float e0 = __expf(-fabsf(v0)), e1 = __expf(-fabsf(v1));
                float2 o;
                o.x = fmaxf(v0, 0.f) + __logf(1.f + e0);
                o.y = fmaxf(v1, 0.f) + __logf(1.f + e1);
                if (col + 1 < N) {
                    *reinterpret_cast<float2*>(orow + col) = o;
                } else if (col < N) {
                    orow[col] = o.x;
                }
            }
        }
    }
}

__global__ void copy_z_kernel(float* __restrict__ out, int n) {
    int i = blockIdx.x * blockDim.x + threadIdx.x;
    if (i < n) out[i] = g_h[i];
}

// ---------------- launch ----------------
extern "C" void kernel_launch(void* const* d_in, const int* in_sizes, int n_in,
                              void* d_out, int out_size) {
    const float* x_seq  = (const float*)d_in[0];
    const void*  ei     = d_in[1];
    const float* ew     = (const float*)d_in[2];
    const float* W1     = (const float*)d_in[3];
    const float* b1     = (const float*)d_in[4];
    const float* W2     = (const float*)d_in[5];
    const float* b2     = (const float*)d_in[6];
    const float* W_ih   = (const float*)d_in[7];
    const float* W_hh   = (const float*)d_in[8];
    const float* b_ih   = (const float*)d_in[9];
    const float* b_hh   = (const float*)d_in[10];
    const float* dec_b  = (const float*)d_in[11];

    const int E = in_sizes[2];
    const int N = in_sizes[0] / (T_STEPS * IN_DIM);
    const int MT = T_STEPS * N;
    float* out = (float*)d_out;

    float *p_aggx, *p_h1, *p_zseq, *p_gi, *p_h;
    uint16_t *p_hh, *p_hl;
    cudaGetSymbolAddress((void**)&p_aggx, g_aggx);
    cudaGetSymbolAddress((void**)&p_h1,   g_h1);
    cudaGetSymbolAddress((void**)&p_zseq, g_zseq);
    cudaGetSymbolAddress((void**)&p_gi,   g_gi);
    cudaGetSymbolAddress((void**)&p_h,    g_h);
    cudaGetSymbolAddress((void**)&p_hh,   g_hh);
    cudaGetSymbolAddress((void**)&p_hl,   g_hl);

    cudaFuncSetAttribute(decode_mma_kernel, cudaFuncAttributeMaxDynamicSharedMemorySize, DSM_TOTAL);

    // --- preprocessing ---
    zero_pre_kernel<<<(N + 255) / 256, 256>>>(N);
    detect_kernel<<<(E + 255) / 256, 256>>>(ei, E, N);
    deg_kernel<<<(E + N + 255) / 256, 256>>>(ei, ew, E, N);
    dinv_kernel<<<(N + 255) / 256, 256>>>(N);
    scan_kernel<<<1, 1024>>>(N);
    scatter_kernel<<<(E + N + 255) / 256, 256>>>(ei, ew, E, N);

    const int aggBlocks = (N * 32 + 255) / 256;

    // --- encoder, batched over all T ---
    agg_kernel<<<aggBlocks, 256>>>(x_seq, p_aggx, nullptr, N);
    {
        dim3 g(1, (MT + 127) / 128);
        sgemm_kernel<<<g, 256>>>(p_aggx, W1, p_h1, MT, HID_DIM, IN_DIM, b1, 1, 0);
    }
    {
        dim3 g(1, (MT + 127) / 128);
        sgemm_kernel<<<g, 256>>>(p_h1, W2, p_aggx, MT, EMB_DIM, HID_DIM, nullptr, 0, 0);
    }
    agg_kernel<<<aggBlocks, 256>>>(p_aggx, p_zseq, b2, N);

    // --- GRU ---
    {
        dim3 g(2, (MT + 127) / 128);
        sgemm_kernel<<<g, 256>>>(p_zseq, W_ih, p_gi, MT, 3 * EMB_DIM, EMB_DIM, b_ih, 2, 1);
    }
    gru_fused_kernel<<<(N + 31) / 32, 256>>>(p_gi, W_hh, b_hh, p_h, N);

    // --- decode via warp-mma bf16-split ---
    split_h_kernel<<<(N * EMB_DIM + 255) / 256, 256>>>(p_h, N * EMB_DIM);
    {
        dim3 g((N + 127) / 128, (N + 127) / 128);
        decode_mma_kernel<<<g, 256, DSM_TOTAL>>>(p_hh, p_hl, out, N, dec_b);
    }
    if ((long long)out_size >= (long long)N * N + (long long)N * EMB_DIM) {
        copy_z_kernel<<<(N * EMB_DIM + 255) / 256, 256>>>(out + (size_t)N * N, N * EMB_DIM);
    }
}

// round 10
// speedup vs baseline: 2.7505x; 1.0099x over previous
#include <cuda_runtime.h>
#include <cuda_bf16.h>
#include <math.h>
#include <stdint.h>

#define T_STEPS 12
#define IN_DIM  64
#define HID_DIM 128
#define EMB_DIM 64
#define NMAX    10000
#define EMAX    320000
#define ETOT    (EMAX + NMAX)
#define FULLM   0xffffffffu

// ---------------- scratch (device globals; no allocation allowed) ----------------
__device__ float g_deg[NMAX];
__device__ float g_dinv[NMAX];
__device__ int   g_cnt[NMAX];
__device__ int   g_fill[NMAX];
__device__ int   g_ptr[NMAX + 1];
__device__ int   g_src[ETOT];
__device__ float g_val[ETOT];
__device__ int   g_idx32;

__device__ float g_aggx[(size_t)T_STEPS * NMAX * IN_DIM];
__device__ float g_zseq[(size_t)T_STEPS * NMAX * EMB_DIM];
__device__ float g_gi  [(size_t)T_STEPS * NMAX * 3 * EMB_DIM];
__device__ float g_h   [(size_t)NMAX * EMB_DIM];
__device__ uint16_t g_hh[(size_t)NMAX * EMB_DIM];
__device__ uint16_t g_hl[(size_t)NMAX * EMB_DIM];

// ---------------- f32x2 helpers ----------------
__device__ __forceinline__ unsigned long long dup2(float a) {
    unsigned long long r;
    asm("mov.b64 %0, {%1, %1};" : "=l"(r) : "f"(a));
    return r;
}
__device__ __forceinline__ unsigned long long pack2(float lo, float hi) {
    unsigned long long r;
    asm("mov.b64 %0, {%1, %2};" : "=l"(r) : "f"(lo), "f"(hi));
    return r;
}
__device__ __forceinline__ void fma2(unsigned long long& acc, unsigned long long a, unsigned long long b) {
    asm("fma.rn.f32x2 %0, %1, %2, %0;" : "+l"(acc) : "l"(a), "l"(b));
}
__device__ __forceinline__ void unpack2(unsigned long long v, float& lo, float& hi) {
    asm("mov.b64 {%0, %1}, %2;" : "=f"(lo), "=f"(hi) : "l"(v));
}
__device__ __forceinline__ float sigm_fast(float x) { return 1.f / (1.f + __expf(-x)); }

__device__ __forceinline__ uint32_t smem_u32(const void* p) {
    uint32_t a;
    asm("{ .reg .u64 t; cvta.to.shared.u64 t, %1; cvt.u32.u64 %0, t; }" : "=r"(a) : "l"(p));
    return a;
}
#define SW128(o) ((o) ^ (((o) >> 3) & 0x70))

// ---------------- warp-level bf16 MMA helpers ----------------
#define LDSM4(r0, r1, r2, r3, addr) \
    asm volatile("ldmatrix.sync.aligned.m8n8.x4.shared.b16 {%0,%1,%2,%3}, [%4];" \
        : "=r"(r0), "=r"(r1), "=r"(r2), "=r"(r3) : "r"(addr))

__device__ __forceinline__ void mma16816(float* c, const uint32_t* a, const uint32_t* b) {
    asm volatile("mma.sync.aligned.m16n8k16.row.col.f32.bf16.bf16.f32 "
        "{%0,%1,%2,%3}, {%4,%5,%6,%7}, {%8,%9}, {%0,%1,%2,%3};"
        : "+f"(c[0]), "+f"(c[1]), "+f"(c[2]), "+f"(c[3])
        : "r"(a[0]), "r"(a[1]), "r"(a[2]), "r"(a[3]), "r"(b[0]), "r"(b[1]));
}

// ---------------- helpers ----------------
__device__ __forceinline__ int load_idx(const void* ei, long long i) {
    if (g_idx32) return ((const int*)ei)[i];
    return (int)(((const long long*)ei)[i]);
}

// ---------------- preprocessing ----------------
__global__ void zero_pre_kernel(int N) {
    int i = blockIdx.x * blockDim.x + threadIdx.x;
    if (i < N) { g_deg[i] = 0.f; g_cnt[i] = 0; g_fill[i] = 0; }
    if (i == 0) g_idx32 = 0;
}

__global__ void detect_kernel(const void* ei, int E, int N) {
    int i = blockIdx.x * blockDim.x + threadIdx.x;
    bool bad = false;
    if (i < E) {
        long long v = ((const long long*)ei)[i];
        bad = (v < 0 || v >= (long long)N);
    }
    if (__any_sync(FULLM, bad)) {
        if ((threadIdx.x & 31) == 0) atomicOr(&g_idx32, 1);
    }
}

__global__ void deg_kernel(const void* ei, const float* __restrict__ ew, int E, int N) {
    int i = blockIdx.x * blockDim.x + threadIdx.x;
    if (i < E) {
        int c = load_idx(ei, (long long)E + i);
        atomicAdd(&g_deg[c], ew[i]);
        atomicAdd(&g_cnt[c], 1);
    } else if (i < E + N) {
        int v = i - E;
        atomicAdd(&g_deg[v], 1.0f);
        atomicAdd(&g_cnt[v], 1);
    }
}

__global__ void dinv_kernel(int N) {
    int i = blockIdx.x * blockDim.x + threadIdx.x;
    if (i < N) {
        float d = g_deg[i];
        g_dinv[i] = (d > 0.f) ? rsqrtf(d) : 0.f;
    }
}

__global__ void scan_kernel(int n) {
    __shared__ int wsum[32];
    const int tid = threadIdx.x, lane = tid & 31, w = tid >> 5;
    int carry = 0;
    for (int base = 0; base < n; base += 1024) {
        int v = (base + tid < n) ? g_cnt[base + tid] : 0;
        int x = v;
        #pragma unroll
        for (int off = 1; off < 32; off <<= 1) {
            int t = __shfl_up_sync(FULLM, x, off);
            if (lane >= off) x += t;
        }
        if (lane == 31) wsum[w] = x;
        __syncthreads();
        if (w == 0) {
            int s = wsum[lane];
            #pragma unroll
            for (int off = 1; off < 32; off <<= 1) {
                int t = __shfl_up_sync(FULLM, s, off);
                if (lane >= off) s += t;
            }
            wsum[lane] = s;
        }
        __syncthreads();
        int woff = (w > 0) ? wsum[w - 1] : 0;
        if (base + tid < n) g_ptr[base + tid] = carry + woff + x - v;
        int tot = wsum[31];
        __syncthreads();
        carry += tot;
    }
    if (tid == 0) g_ptr[n] = carry;
}

__global__ void scatter_kernel(const void* ei, const float* __restrict__ ew, int E, int N) {
    int i = blockIdx.x * blockDim.x + threadIdx.x;
    if (i < E) {
        int r = load_idx(ei, i);
        int c = load_idx(ei, (long long)E + i);
        int p = g_ptr[c] + atomicAdd(&g_fill[c], 1);
        g_src[p] = r;
        g_val[p] = g_dinv[r] * ew[i] * g_dinv[c];
    } else if (i < E + N) {
        int v = i - E;
        int p = g_ptr[v] + atomicAdd(&g_fill[v], 1);
        g_src[p] = v;
        g_val[p] = g_dinv[v] * g_dinv[v];
    }
}

// ---------------- batched (over T) 64-dim aggregation (float4 loads) -------------
// lane covers 4 columns (cq..cq+3); lanes 0-15 handle even timesteps, 16-31 odd.
__global__ void agg_kernel(const float* __restrict__ src, float* __restrict__ dst,
                           const float* __restrict__ bias, int N) {
    int warp = (blockIdx.x * blockDim.x + threadIdx.x) >> 5;
    int lane = threadIdx.x & 31;
    if (warp >= N) return;
    int e0 = g_ptr[warp], e1 = g_ptr[warp + 1];
    const int cq = (lane & 15) * 4;
    const int thalf = lane >> 4;
    const size_t tstride = (size_t)N * 64;

    unsigned long long acc2[6][2];
    #pragma unroll
    for (int t = 0; t < 6; t++) { acc2[t][0] = 0ull; acc2[t][1] = 0ull; }

    for (int e = e0; e < e1; e += 32) {
        int got = e1 - e; if (got > 32) got = 32;
        int r = 0; float v = 0.f;
        if (lane < got) { r = g_src[e + lane]; v = g_val[e + lane]; }
        for (int j = 0; j < got; j++) {
            int   rr = __shfl_sync(FULLM, r, j);
            float vv = __shfl_sync(FULLM, v, j);
            unsigned long long v2 = dup2(vv);
            const float* base = src + (size_t)rr * 64 + cq + thalf * tstride;
            #pragma unroll
            for (int tt = 0; tt < 6; tt++) {
                ulonglong2 x = *reinterpret_cast<const ulonglong2*>(base + 2 * tt * tstride);
                fma2(acc2[tt][0], v2, x.x);
                fma2(acc2[tt][1], v2, x.y);
            }
        }
    }
    float b0 = 0.f, b1_ = 0.f, b2 = 0.f, b3 = 0.f;
    if (bias) { b0 = bias[cq]; b1_ = bias[cq + 1]; b2 = bias[cq + 2]; b3 = bias[cq + 3]; }
    #pragma unroll
    for (int tt = 0; tt < 6; tt++) {
        int tp = 2 * tt + thalf;
        float a0, a1, a2, a3;
        unpack2(acc2[tt][0], a0, a1);
        unpack2(acc2[tt][1], a2, a3);
        float4 o; o.x = a0 + b0; o.y = a1 + b1_; o.z = a2 + b2; o.w = a3 + b3;
        *reinterpret_cast<float4*>(dst + (size_t)tp * tstride + (size_t)warp * 64 + cq) = o;
    }
}

// ---------------- generic SGEMM (f32x2 inner) — used for GI projection ----------
__global__ __launch_bounds__(256, 2) void sgemm_kernel(
    const float* __restrict__ A, const float* __restrict__ B, float* __restrict__ C,
    int M, int N, int K, const float* __restrict__ bias, int epi, int transB)
{
    __shared__ __align__(16) float As[8][128];
    __shared__ __align__(16) float Bs[8][128];
    const int tid = threadIdx.x;
    const int bm = blockIdx.y * 128;
    const int bn = blockIdx.x * 128;
    const int tr = (tid / 16) * 8;
    const int tc = (tid % 16) * 8;

    unsigned long long acc2[8][4];
    #pragma unroll
    for (int i = 0; i < 8; i++)
        #pragma unroll
        for (int j = 0; j < 4; j++) acc2[i][j] = 0ull;

    const int arow = tid >> 1;
    const int acol = (tid & 1) * 4;

    for (int kt = 0; kt < K; kt += 8) {
        float4 av = make_float4(0.f, 0.f, 0.f, 0.f);
        if (bm + arow < M)
            av = *reinterpret_cast<const float4*>(A + (size_t)(bm + arow) * K + kt + acol);
        As[acol + 0][arow] = av.x; As[acol + 1][arow] = av.y;
        As[acol + 2][arow] = av.z; As[acol + 3][arow] = av.w;

        if (!transB) {
            int kr = tid >> 5;
            int cc = (tid & 31) * 4;
            float4 bv = make_float4(0.f, 0.f, 0.f, 0.f);
            if (bn + cc < N)
                bv = *reinterpret_cast<const float4*>(B + (size_t)(kt + kr) * N + bn + cc);
            *reinterpret_cast<float4*>(&Bs[kr][cc]) = bv;
        } else {
            int cc = tid >> 1;
            int kk = (tid & 1) * 4;
            float4 bv = make_float4(0.f, 0.f, 0.f, 0.f);
            if (bn + cc < N)
                bv = *reinterpret_cast<const float4*>(B + (size_t)(bn + cc) * K + kt + kk);
            Bs[kk + 0][cc] = bv.x; Bs[kk + 1][cc] = bv.y;
            Bs[kk + 2][cc] = bv.z; Bs[kk + 3][cc] = bv.w;
        }
        __syncthreads();

        #pragma unroll
        for (int k = 0; k < 8; k++) {
            float ar[8];
            *reinterpret_cast<float4*>(ar)     = *reinterpret_cast<const float4*>(&As[k][tr]);
            *reinterpret_cast<float4*>(ar + 4) = *reinterpret_cast<const float4*>(&As[k][tr + 4]);
            ulonglong2 b0 = *reinterpret_cast<const ulonglong2*>(&Bs[k][tc]);
            ulonglong2 b1 = *reinterpret_cast<const ulonglong2*>(&Bs[k][tc + 4]);
            #pragma unroll
            for (int i = 0; i < 8; i++) {
                unsigned long long ad = dup2(ar[i]);
                fma2(acc2[i][0], ad, b0.x);
                fma2(acc2[i][1], ad, b0.y);
                fma2(acc2[i][2], ad, b1.x);
                fma2(acc2[i][3], ad, b1.y);
            }
        }
        __syncthreads();
    }

    #pragma unroll
    for (int i = 0; i < 8; i++) {
        int r = bm + tr + i;
        if (r >= M) continue;
        float acc[8];
        #pragma unroll
        for (int jp = 0; jp < 4; jp++) unpack2(acc2[i][jp], acc[2 * jp], acc[2 * jp + 1]);
        #pragma unroll
        for (int jj = 0; jj < 8; jj += 4) {
            int c = bn + tc + jj;
            if (c >= N) continue;
            float4 v4;
            float* vp = reinterpret_cast<float*>(&v4);
            #pragma unroll
            for (int q = 0; q < 4; q++) {
                float v = acc[jj + q];
                if (epi == 1)      { v += bias[c + q]; v = fmaxf(v, 0.f); }
                else if (epi == 2) { v += bias[c + q]; }
                vp[q] = v;
            }
            *reinterpret_cast<float4*>(C + (size_t)r * N + c) = v4;
        }
    }
}

// ---------------- fused encoder GEMM: P = relu(A@W1 + b1) @ W2 ------------------
// A[M,64], W1[64,128], W2[128,64]. H1 tile (128x128) kept in swizzled smem.
#define FSM_FLOATS (1024 + 1024 + 8192 + 16384)
#define FSM_BYTES  (FSM_FLOATS * 4)

__global__ __launch_bounds__(256) void enc_fused_kernel(
    const float* __restrict__ A, const float* __restrict__ W1, const float* __restrict__ b1,
    const float* __restrict__ W2, float* __restrict__ P, int M)
{
    extern __shared__ __align__(16) float fs[];
    float* As  = fs;          // [8][128] k-major
    float* Bs  = fs + 1024;   // [8][128]
    float* W2s = fs + 2048;   // [128][64]
    float* Hs  = fs + 10240;  // 128x128, XOR-swizzled: (r,k) -> [k*128 + ((r>>2 ^ (k>>3))&31)*4 + (r&3)]
    const int tid = threadIdx.x;
    const int bm = blockIdx.x * 128;

    // load all of W2 (covered by first __syncthreads below)
    for (int i = tid; i < 2048; i += 256)
        reinterpret_cast<float4*>(W2s)[i] = reinterpret_cast<const float4*>(W2)[i];

    // ---- stage 1: H = relu(A @ W1 + b1) ----
    const int tr = (tid / 16) * 8;
    const int tc = (tid % 16) * 8;
    unsigned long long acc2[8][4];
    #pragma unroll
    for (int i = 0; i < 8; i++)
        #pragma unroll
        for (int j = 0; j < 4; j++) acc2[i][j] = 0ull;

    const int arow = tid >> 1;
    const int acol = (tid & 1) * 4;

    #pragma unroll
    for (int kt = 0; kt < 64; kt += 8) {
        float4 av = make_float4(0.f, 0.f, 0.f, 0.f);
        if (bm + arow < M)
            av = *reinterpret_cast<const float4*>(A + (size_t)(bm + arow) * 64 + kt + acol);
        As[(acol + 0) * 128 + arow] = av.x; As[(acol + 1) * 128 + arow] = av.y;
        As[(acol + 2) * 128 + arow] = av.z; As[(acol + 3) * 128 + arow] = av.w;
        {
            int kr = tid >> 5, cc = (tid & 31) * 4;
            *reinterpret_cast<float4*>(&Bs[kr * 128 + cc]) =
                *reinterpret_cast<const float4*>(W1 + (size_t)(kt + kr) * 128 + cc);
        }
        __syncthreads();
        #pragma unroll
        for (int k = 0; k < 8; k++) {
            float ar[8];
            *reinterpret_cast<float4*>(ar)     = *reinterpret_cast<const float4*>(&As[k * 128 + tr]);
            *reinterpret_cast<float4*>(ar + 4) = *reinterpret_cast<const float4*>(&As[k * 128 + tr + 4]);
            ulonglong2 b0 = *reinterpret_cast<const ulonglong2*>(&Bs[k * 128 + tc]);
            ulonglong2 b1v = *reinterpret_cast<const ulonglong2*>(&Bs[k * 128 + tc + 4]);
            #pragma unroll
            for (int i = 0; i < 8; i++) {
                unsigned long long ad = dup2(ar[i]);
                fma2(acc2[i][0], ad, b0.x);
                fma2(acc2[i][1], ad, b0.y);
                fma2(acc2[i][2], ad, b1v.x);
                fma2(acc2[i][3], ad, b1v.y);
            }
        }
        __syncthreads();
    }

    // epilogue: relu+bias -> swizzled Hs
    #pragma unroll
    for (int i = 0; i < 8; i++) {
        int r = tr + i;
        float acc[8];
        #pragma unroll
        for (int jp = 0; jp < 4; jp++) unpack2(acc2[i][jp], acc[2 * jp], acc[2 * jp + 1]);
        #pragma unroll
        for (int j = 0; j < 8; j++) {
            int k = tc + j;
            float v = fmaxf(acc[j] + b1[k], 0.f);
            Hs[k * 128 + ((((r >> 2) ^ (k >> 3)) & 31) << 2) + (r & 3)] = v;
        }
    }
    __syncthreads();

    // ---- stage 2: P_tile = H @ W2 ----
    const int tr2 = (tid >> 3) * 4;
    const int tc2 = (tid & 7) * 8;
    unsigned long long pacc[4][4];
    #pragma unroll
    for (int i = 0; i < 4; i++)
        #pragma unroll
        for (int j = 0; j < 4; j++) pacc[i][j] = 0ull;

    #pragma unroll 8
    for (int k = 0; k < 128; k++) {
        float4 a4 = *reinterpret_cast<const float4*>(
            &Hs[k * 128 + ((((tr2 >> 2) ^ (k >> 3)) & 31) << 2)]);
        ulonglong2 b0 = *reinterpret_cast<const ulonglong2*>(&W2s[k * 64 + tc2]);
        ulonglong2 b1v = *reinterpret_cast<const ulonglong2*>(&W2s[k * 64 + tc2 + 4]);
        float aa[4] = {a4.x, a4.y, a4.z, a4.w};
        #pragma unroll
        for (int i = 0; i < 4; i++) {
            unsigned long long ad = dup2(aa[i]);
            fma2(pacc[i][0], ad, b0.x);
            fma2(pacc[i][1], ad, b0.y);
            fma2(pacc[i][2], ad, b1v.x);
            fma2(pacc[i][3], ad, b1v.y);
        }
    }
    #pragma unroll
    for (int i = 0; i < 4; i++) {
        int r = bm + tr2 + i;
        if (r >= M) continue;
        float o[8];
        #pragma unroll
        for (int jp = 0; jp < 4; jp++) unpack2(pacc[i][jp], o[2 * jp], o[2 * jp + 1]);
        *reinterpret_cast<float4*>(P + (size_t)r * 64 + tc2)     = make_float4(o[0], o[1], o[2], o[3]);
        *reinterpret_cast<float4*>(P + (size_t)r * 64 + tc2 + 4) = make_float4(o[4], o[5], o[6], o[7]);
    }
}

// ---------------- fused GRU: 4 nodes/warp, f32x2; writes h + bf16 split ----------
__global__ __launch_bounds__(256) void gru_fused_kernel(
    const float* __restrict__ gi, const float* __restrict__ Whh,
    const float* __restrict__ bhh, float* __restrict__ h, int N)
{
    __shared__ __align__(16) float4 ws4[3 * 32 * 32];
    const int tid = threadIdx.x;
    for (int idx = tid; idx < 3 * 32 * 32; idx += 256) {
        int lane_ = idx & 31;
        int k2 = (idx >> 5) & 31;
        int g = idx >> 10;
        float4 f;
        f.x = Whh[(size_t)(g * 64 + lane_) * 64 + 2 * k2];
        f.y = Whh[(size_t)(g * 64 + 32 + lane_) * 64 + 2 * k2];
        f.z = Whh[(size_t)(g * 64 + lane_) * 64 + 2 * k2 + 1];
        f.w = Whh[(size_t)(g * 64 + 32 + lane_) * 64 + 2 * k2 + 1];
        ws4[idx] = f;
    }
    __syncthreads();

    const int warp = tid >> 5, lane = tid & 31;
    const int node0 = (blockIdx.x * 8 + warp) * 4;
    if (node0 >= N) return;

    const unsigned long long bR = pack2(bhh[lane],       bhh[32 + lane]);
    const unsigned long long bZ = pack2(bhh[64 + lane],  bhh[96 + lane]);
    const unsigned long long bN = pack2(bhh[128 + lane], bhh[160 + lane]);

    float hA[4] = {0.f, 0.f, 0.f, 0.f}, hB[4] = {0.f, 0.f, 0.f, 0.f};

    const float4* wR = ws4;
    const float4* wZ = ws4 + 32 * 32;
    const float4* wN = ws4 + 2 * 32 * 32;

    #pragma unroll 1
    for (int t = 0; t < T_STEPS; t++) {
        float2 giR[4], giZ[4], giN[4];
        #pragma unroll
        for (int j = 0; j < 4; j++) {
            int node = node0 + j;
            if (node < N) {
                const float* gr = gi + ((size_t)t * N + node) * 192;
                giR[j] = make_float2(gr[lane],       gr[32 + lane]);
                giZ[j] = make_float2(gr[64 + lane],  gr[96 + lane]);
                giN[j] = make_float2(gr[128 + lane], gr[160 + lane]);
            } else {
                giR[j] = giZ[j] = giN[j] = make_float2(0.f, 0.f);
            }
        }

        unsigned long long aR[4], aZ[4], aN[4];
        #pragma unroll
        for (int j = 0; j < 4; j++) { aR[j] = bR; aZ[j] = bZ; aN[j] = bN; }

        if (t > 0) {
            #pragma unroll
            for (int k2 = 0; k2 < 32; k2++) {
                float4 r4 = wR[k2 * 32 + lane];
                float4 z4 = wZ[k2 * 32 + lane];
                float4 n4 = wN[k2 * 32 + lane];
                unsigned long long r0 = pack2(r4.x, r4.y), r1 = pack2(r4.z, r4.w);
                unsigned long long z0 = pack2(z4.x, z4.y), z1 = pack2(z4.z, z4.w);
                unsigned long long n0 = pack2(n4.x, n4.y), n1 = pack2(n4.z, n4.w);
                #pragma unroll
                for (int j = 0; j < 4; j++) {
                    float h0, h1;
                    if (k2 < 16) {
                        h0 = __shfl_sync(FULLM, hA[j], 2 * k2);
                        h1 = __shfl_sync(FULLM, hA[j], 2 * k2 + 1);
                    } else {
                        h0 = __shfl_sync(FULLM, hB[j], 2 * k2 - 32);
                        h1 = __shfl_sync(FULLM, hB[j], 2 * k2 - 31);
                    }
                    unsigned long long d0 = dup2(h0), d1 = dup2(h1);
                    fma2(aR[j], d0, r0); fma2(aR[j], d1, r1);
                    fma2(aZ[j], d0, z0); fma2(aZ[j], d1, z1);
                    fma2(aN[j], d0, n0); fma2(aN[j], d1, n1);
                }
            }
        }

        #pragma unroll
        for (int j = 0; j < 4; j++) {
            float aRlo, aRhi, aZlo, aZhi, aNlo, aNhi;
            unpack2(aR[j], aRlo, aRhi);
            unpack2(aZ[j], aZlo, aZhi);
            unpack2(aN[j], aNlo, aNhi);
            float rg1 = sigm_fast(giR[j].x + aRlo), rg2 = sigm_fast(giR[j].y + aRhi);
            float zg1 = sigm_fast(giZ[j].x + aZlo), zg2 = sigm_fast(giZ[j].y + aZhi);
            float n1 = tanhf(giN[j].x + rg1 * aNlo), n2 = tanhf(giN[j].y + rg2 * aNhi);
            hA[j] = (1.f - zg1) * n1 + zg1 * hA[j];
            hB[j] = (1.f - zg2) * n2 + zg2 * hB[j];
        }
    }

    #pragma unroll
    for (int j = 0; j < 4; j++) {
        int node = node0 + j;
        if (node < N) {
            size_t o1 = (size_t)node * 64 + lane;
            size_t o2 = o1 + 32;
            h[o1] = hA[j]; h[o2] = hB[j];
            __nv_bfloat16 bh1 = __float2bfloat16(hA[j]);
            __nv_bfloat16 bh2 = __float2bfloat16(hB[j]);
            g_hh[o1] = __bfloat16_as_ushort(bh1);
            g_hh[o2] = __bfloat16_as_ushort(bh2);
            g_hl[o1] = __bfloat16_as_ushort(__float2bfloat16(hA[j] - __bfloat162float(bh1)));
            g_hl[o2] = __bfloat16_as_ushort(__float2bfloat16(hB[j] - __bfloat162float(bh2)));
        }
    }
}

// ---------------- decode via warp-level bf16 mma: out = softplus(H H^T + b) ------
#define DSM_AHI 0
#define DSM_ALO 16384
#define DSM_BHI 32768
#define DSM_BLO 49152
#define DSM_TOTAL 65536

__global__ __launch_bounds__(256, 1) void decode_mma_kernel(
    const uint16_t* __restrict__ Hh, const uint16_t* __restrict__ Hl,
    float* __restrict__ out, int N, const float* __restrict__ dec_b)
{
    extern __shared__ __align__(1024) char smem[];
    const uint32_t sb = smem_u32(smem);
    const int tid = threadIdx.x;
    const int wid = tid >> 5, lane = tid & 31;
    const int bm = blockIdx.y * 128;
    const int bn = blockIdx.x * 128;

    {
        const uint16_t* srcs[4]  = { Hh, Hl, Hh, Hl };
        const int       bases[4] = { bm, bm, bn, bn };
        const int       offs[4]  = { DSM_AHI, DSM_ALO, DSM_BHI, DSM_BLO };
        #pragma unroll
        for (int m = 0; m < 4; m++) {
            const uint16_t* s = srcs[m];
            int gb = bases[m], off = offs[m];
            for (int ck = tid; ck < 1024; ck += 256) {
                int row = ck >> 3, cc = ck & 7;
                uint4 v = make_uint4(0u, 0u, 0u, 0u);
                int gr = gb + row;
                if (gr < N) v = *reinterpret_cast<const uint4*>(s + (size_t)gr * 64 + cc * 8);
                int bo = row * 128 + cc * 16;
                *reinterpret_cast<uint4*>(smem + off + SW128(bo)) = v;
            }
        }
    }
    __syncthreads();

    const int mrow = (wid & 1) * 64;
    const int ncol = (wid >> 1) * 32;

    float acc[4][4][4];
    #pragma unroll
    for (int i = 0; i < 4; i++)
        #pragma unroll
        for (int j = 0; j < 4; j++)
            #pragma unroll
            for (int q = 0; q < 4; q++) acc[i][j][q] = 0.f;

    const int a_r  = mrow + (lane & 15);
    const int a_kh = (lane >> 4) * 16;
    // packed B ldmatrix.x4: lane groups of 8 -> (nf, khalf) quadrants
    const int b_rp  = ncol + ((lane >> 4) & 1) * 8 + (lane & 7);
    const int b_khp = ((lane >> 3) & 1) * 16;

    #pragma unroll
    for (int ks = 0; ks < 4; ks++) {
        const int kb = ks * 32;
        uint32_t ah[4][4], al[4][4], bh[4][2], bl[4][2];
        #pragma unroll
        for (int mf = 0; mf < 4; mf++) {
            LDSM4(ah[mf][0], ah[mf][1], ah[mf][2], ah[mf][3],
                  sb + DSM_AHI + SW128((a_r + mf * 16) * 128 + kb + a_kh));
            LDSM4(al[mf][0], al[mf][1], al[mf][2], al[mf][3],
                  sb + DSM_ALO + SW128((a_r + mf * 16) * 128 + kb + a_kh));
        }
        LDSM4(bh[0][0], bh[0][1], bh[1][0], bh[1][1],
              sb + DSM_BHI + SW128(b_rp * 128 + kb + b_khp));
        LDSM4(bh[2][0], bh[2][1], bh[3][0], bh[3][1],
              sb + DSM_BHI + SW128((b_rp + 16) * 128 + kb + b_khp));
        LDSM4(bl[0][0], bl[0][1], bl[1][0], bl[1][1],
              sb + DSM_BLO + SW128(b_rp * 128 + kb + b_khp));
        LDSM4(bl[2][0], bl[2][1], bl[3][0], bl[3][1],
              sb + DSM_BLO + SW128((b_rp + 16) * 128 + kb + b_khp));

        #pragma unroll
        for (int mf = 0; mf < 4; mf++)
            #pragma unroll
            for (int nf = 0; nf < 4; nf++) {
                mma16816(acc[mf][nf], ah[mf], bh[nf]);
                mma16816(acc[mf][nf], ah[mf], bl[nf]);
                mma16816(acc[mf][nf], al[mf], bh[nf]);
            }
    }

    const float bsc = dec_b[0];
    const int rr0 = bm + mrow + (lane >> 2);
    const int cc0 = bn + ncol + 2 * (lane & 3);
    #pragma unroll
    for (int mf = 0; mf < 4; mf++) {
        #pragma unroll
        for (int half = 0; half < 2; half++) {
            int row = rr0 + mf * 16 + half * 8;
            if (row >= N) continue;
            float* orow = out + (size_t)row * N;
            #pragma unroll
            for (int nf = 0; nf < 4; nf++) {
                int col = cc0 + nf * 8;
                if (col + 1 >= N && col >= N) continue;
                float v0 = acc[mf][nf][half * 2 + 0] + bsc;
                float v1 = acc[mf][nf][half * 2 + 1] + bsc;
                float e0 = __expf(-fabsf(v0)), e1 = __expf(-fabsf(v1));
                float2 o;
                o.x = fmaxf(v0, 0.f) + __logf(1.f + e0);
                o.y = fmaxf(v1, 0.f) + __logf(1.f + e1);
                if (col + 1 < N) {
                    *reinterpret_cast<float2*>(orow + col) = o;
                } else if (col < N) {
                    orow[col] = o.x;
                }
            }
        }
    }
}

__global__ void copy_z_kernel(float* __restrict__ out, int n) {
    int i = blockIdx.x * blockDim.x + threadIdx.x;
    if (i < n) out[i] = g_h[i];
}

// ---------------- launch ----------------
extern "C" void kernel_launch(void* const* d_in, const int* in_sizes, int n_in,
                              void* d_out, int out_size) {
    const float* x_seq  = (const float*)d_in[0];
    const void*  ei     = d_in[1];
    const float* ew     = (const float*)d_in[2];
    const float* W1     = (const float*)d_in[3];
    const float* b1     = (const float*)d_in[4];
    const float* W2     = (const float*)d_in[5];
    const float* b2     = (const float*)d_in[6];
    const float* W_ih   = (const float*)d_in[7];
    const float* W_hh   = (const float*)d_in[8];
    const float* b_ih   = (const float*)d_in[9];
    const float* b_hh   = (const float*)d_in[10];
    const float* dec_b  = (const float*)d_in[11];

    const int E = in_sizes[2];
    const int N = in_sizes[0] / (T_STEPS * IN_DIM);
    const int MT = T_STEPS * N;
    float* out = (float*)d_out;

    float *p_aggx, *p_zseq, *p_gi, *p_h;
    uint16_t *p_hh, *p_hl;
    cudaGetSymbolAddress((void**)&p_aggx, g_aggx);
    cudaGetSymbolAddress((void**)&p_zseq, g_zseq);
    cudaGetSymbolAddress((void**)&p_gi,   g_gi);
    cudaGetSymbolAddress((void**)&p_h,    g_h);
    cudaGetSymbolAddress((void**)&p_hh,   g_hh);
    cudaGetSymbolAddress((void**)&p_hl,   g_hl);

    cudaFuncSetAttribute(decode_mma_kernel, cudaFuncAttributeMaxDynamicSharedMemorySize, DSM_TOTAL);
    cudaFuncSetAttribute(enc_fused_kernel,  cudaFuncAttributeMaxDynamicSharedMemorySize, FSM_BYTES);

    // --- preprocessing ---
    zero_pre_kernel<<<(N + 255) / 256, 256>>>(N);
    detect_kernel<<<(E + 255) / 256, 256>>>(ei, E, N);
    deg_kernel<<<(E + N + 255) / 256, 256>>>(ei, ew, E, N);
    dinv_kernel<<<(N + 255) / 256, 256>>>(N);
    scan_kernel<<<1, 1024>>>(N);
    scatter_kernel<<<(E + N + 255) / 256, 256>>>(ei, ew, E, N);

    const int aggBlocks = (N * 32 + 255) / 256;

    // --- encoder, batched over all T ---
    agg_kernel<<<aggBlocks, 256>>>(x_seq, p_aggx, nullptr, N);
    // P = relu(aggx@W1+b1)@W2, fused; write into zseq buffer temporarily? No —
    // write into g_gi region? P must survive until agg2 reads it. Use p_zseq as P,
    // then agg2 reads p_zseq and writes ... into p_aggx (free by then).
    enc_fused_kernel<<<(MT + 127) / 128, 256, FSM_BYTES>>>(p_aggx, W1, b1, W2, p_zseq, MT);
    agg_kernel<<<aggBlocks, 256>>>(p_zseq, p_aggx, b2, N);   // zseq_final -> p_aggx

    // --- GRU: GI = zseq_final @ W_ih^T + b_ih ---
    {
        dim3 g(2, (MT + 127) / 128);
        sgemm_kernel<<<g, 256>>>(p_aggx, W_ih, p_gi, MT, 3 * EMB_DIM, EMB_DIM, b_ih, 2, 1);
    }
    gru_fused_kernel<<<(N + 31) / 32, 256>>>(p_gi, W_hh, b_hh, p_h, N);

    // --- decode via warp-mma bf16-split (hh/hl written by GRU) ---
    {
        dim3 g((N + 127) / 128, (N + 127) / 128);
        decode_mma_kernel<<<g, 256, DSM_TOTAL>>>(p_hh, p_hl, out, N, dec_b);
    }
    if ((long long)out_size >= (long long)N * N + (long long)N * EMB_DIM) {
        copy_z_kernel<<<(N * EMB_DIM + 255) / 256, 256>>>(out + (size_t)N * N, N * EMB_DIM);
    }
}

// round 16
// speedup vs baseline: 2.8237x; 1.0266x over previous
#include <cuda_runtime.h>
#include <cuda_bf16.h>
#include <math.h>
#include <stdint.h>

#define T_STEPS 12
#define IN_DIM  64
#define HID_DIM 128
#define EMB_DIM 64
#define NMAX    10000
#define EMAX    320000
#define ETOT    (EMAX + NMAX)
#define FULLM   0xffffffffu

// ---------------- scratch (device globals; no allocation allowed) ----------------
__device__ float g_deg[NMAX];
__device__ float g_dinv[NMAX];
__device__ int   g_cnt[NMAX];
__device__ int   g_fill[NMAX];
__device__ int   g_ptr[NMAX + 1];
__device__ int   g_src[ETOT];
__device__ float g_val[ETOT];
__device__ int   g_idx32;

__device__ float g_aggx[(size_t)T_STEPS * NMAX * IN_DIM];
__device__ float g_zseq[(size_t)T_STEPS * NMAX * EMB_DIM];
__device__ float g_gi  [(size_t)T_STEPS * NMAX * 3 * EMB_DIM];
__device__ float g_h   [(size_t)NMAX * EMB_DIM];
__device__ uint16_t g_hh[(size_t)NMAX * EMB_DIM];
__device__ uint16_t g_hl[(size_t)NMAX * EMB_DIM];

// ---------------- f32x2 helpers ----------------
__device__ __forceinline__ unsigned long long dup2(float a) {
    unsigned long long r;
    asm("mov.b64 %0, {%1, %1};" : "=l"(r) : "f"(a));
    return r;
}
__device__ __forceinline__ unsigned long long pack2(float lo, float hi) {
    unsigned long long r;
    asm("mov.b64 %0, {%1, %2};" : "=l"(r) : "f"(lo), "f"(hi));
    return r;
}
__device__ __forceinline__ void fma2(unsigned long long& acc, unsigned long long a, unsigned long long b) {
    asm("fma.rn.f32x2 %0, %1, %2, %0;" : "+l"(acc) : "l"(a), "l"(b));
}
__device__ __forceinline__ void unpack2(unsigned long long v, float& lo, float& hi) {
    asm("mov.b64 {%0, %1}, %2;" : "=f"(lo), "=f"(hi) : "l"(v));
}
__device__ __forceinline__ float sigm_fast(float x) { return 1.f / (1.f + __expf(-x)); }

__device__ __forceinline__ uint32_t smem_u32(const void* p) {
    uint32_t a;
    asm("{ .reg .u64 t; cvta.to.shared.u64 t, %1; cvt.u32.u64 %0, t; }" : "=r"(a) : "l"(p));
    return a;
}
#define SW128(o) ((o) ^ (((o) >> 3) & 0x70))

// ---------------- warp-level bf16 MMA helpers ----------------
#define LDSM4(r0, r1, r2, r3, addr) \
    asm volatile("ldmatrix.sync.aligned.m8n8.x4.shared.b16 {%0,%1,%2,%3}, [%4];" \
        : "=r"(r0), "=r"(r1), "=r"(r2), "=r"(r3) : "r"(addr))

__device__ __forceinline__ void mma16816(float* c, const uint32_t* a, const uint32_t* b) {
    asm volatile("mma.sync.aligned.m16n8k16.row.col.f32.bf16.bf16.f32 "
        "{%0,%1,%2,%3}, {%4,%5,%6,%7}, {%8,%9}, {%0,%1,%2,%3};"
        : "+f"(c[0]), "+f"(c[1]), "+f"(c[2]), "+f"(c[3])
        : "r"(a[0]), "r"(a[1]), "r"(a[2]), "r"(a[3]), "r"(b[0]), "r"(b[1]));
}

// ---------------- helpers ----------------
__device__ __forceinline__ int load_idx(const void* ei, long long i) {
    if (g_idx32) return ((const int*)ei)[i];
    return (int)(((const long long*)ei)[i]);
}

// ---------------- preprocessing ----------------
__global__ void zero_pre_kernel(int N) {
    int i = blockIdx.x * blockDim.x + threadIdx.x;
    if (i < N) { g_deg[i] = 0.f; g_cnt[i] = 0; g_fill[i] = 0; }
    if (i == 0) g_idx32 = 0;
}

__global__ void detect_kernel(const void* ei, int E, int N) {
    int i = blockIdx.x * blockDim.x + threadIdx.x;
    bool bad = false;
    if (i < E) {
        long long v = ((const long long*)ei)[i];
        bad = (v < 0 || v >= (long long)N);
    }
    if (__any_sync(FULLM, bad)) {
        if ((threadIdx.x & 31) == 0) atomicOr(&g_idx32, 1);
    }
}

__global__ void deg_kernel(const void* ei, const float* __restrict__ ew, int E, int N) {
    int i = blockIdx.x * blockDim.x + threadIdx.x;
    if (i < E) {
        int c = load_idx(ei, (long long)E + i);
        atomicAdd(&g_deg[c], ew[i]);
        atomicAdd(&g_cnt[c], 1);
    } else if (i < E + N) {
        int v = i - E;
        atomicAdd(&g_deg[v], 1.0f);
        atomicAdd(&g_cnt[v], 1);
    }
}

__global__ void dinv_kernel(int N) {
    int i = blockIdx.x * blockDim.x + threadIdx.x;
    if (i < N) {
        float d = g_deg[i];
        g_dinv[i] = (d > 0.f) ? rsqrtf(d) : 0.f;
    }
}

__global__ void scan_kernel(int n) {
    __shared__ int wsum[32];
    const int tid = threadIdx.x, lane = tid & 31, w = tid >> 5;
    int carry = 0;
    for (int base = 0; base < n; base += 1024) {
        int v = (base + tid < n) ? g_cnt[base + tid] : 0;
        int x = v;
        #pragma unroll
        for (int off = 1; off < 32; off <<= 1) {
            int t = __shfl_up_sync(FULLM, x, off);
            if (lane >= off) x += t;
        }
        if (lane == 31) wsum[w] = x;
        __syncthreads();
        if (w == 0) {
            int s = wsum[lane];
            #pragma unroll
            for (int off = 1; off < 32; off <<= 1) {
                int t = __shfl_up_sync(FULLM, s, off);
                if (lane >= off) s += t;
            }
            wsum[lane] = s;
        }
        __syncthreads();
        int woff = (w > 0) ? wsum[w - 1] : 0;
        if (base + tid < n) g_ptr[base + tid] = carry + woff + x - v;
        int tot = wsum[31];
        __syncthreads();
        carry += tot;
    }
    if (tid == 0) g_ptr[n] = carry;
}

__global__ void scatter_kernel(const void* ei, const float* __restrict__ ew, int E, int N) {
    int i = blockIdx.x * blockDim.x + threadIdx.x;
    if (i < E) {
        int r = load_idx(ei, i);
        int c = load_idx(ei, (long long)E + i);
        int p = g_ptr[c] + atomicAdd(&g_fill[c], 1);
        g_src[p] = r;
        g_val[p] = g_dinv[r] * ew[i] * g_dinv[c];
    } else if (i < E + N) {
        int v = i - E;
        int p = g_ptr[v] + atomicAdd(&g_fill[v], 1);
        g_src[p] = v;
        g_val[p] = g_dinv[v] * g_dinv[v];
    }
}

// ---------------- batched (over T) 64-dim aggregation (float4 loads) -------------
// lane covers 4 columns (cq..cq+3); lanes 0-15 handle even timesteps, 16-31 odd.
__global__ void agg_kernel(const float* __restrict__ src, float* __restrict__ dst,
                           const float* __restrict__ bias, int N) {
    int warp = (blockIdx.x * blockDim.x + threadIdx.x) >> 5;
    int lane = threadIdx.x & 31;
    if (warp >= N) return;
    int e0 = g_ptr[warp], e1 = g_ptr[warp + 1];
    const int cq = (lane & 15) * 4;
    const int thalf = lane >> 4;
    const size_t tstride = (size_t)N * 64;

    unsigned long long acc2[6][2];
    #pragma unroll
    for (int t = 0; t < 6; t++) { acc2[t][0] = 0ull; acc2[t][1] = 0ull; }

    for (int e = e0; e < e1; e += 32) {
        int got = e1 - e; if (got > 32) got = 32;
        int r = 0; float v = 0.f;
        if (lane < got) { r = g_src[e + lane]; v = g_val[e + lane]; }
        for (int j = 0; j < got; j++) {
            int   rr = __shfl_sync(FULLM, r, j);
            float vv = __shfl_sync(FULLM, v, j);
            unsigned long long v2 = dup2(vv);
            const float* base = src + (size_t)rr * 64 + cq + thalf * tstride;
            #pragma unroll
            for (int tt = 0; tt < 6; tt++) {
                ulonglong2 x = *reinterpret_cast<const ulonglong2*>(base + 2 * tt * tstride);
                fma2(acc2[tt][0], v2, x.x);
                fma2(acc2[tt][1], v2, x.y);
            }
        }
    }
    float b0 = 0.f, b1_ = 0.f, b2 = 0.f, b3 = 0.f;
    if (bias) { b0 = bias[cq]; b1_ = bias[cq + 1]; b2 = bias[cq + 2]; b3 = bias[cq + 3]; }
    #pragma unroll
    for (int tt = 0; tt < 6; tt++) {
        int tp = 2 * tt + thalf;
        float a0, a1, a2, a3;
        unpack2(acc2[tt][0], a0, a1);
        unpack2(acc2[tt][1], a2, a3);
        float4 o; o.x = a0 + b0; o.y = a1 + b1_; o.z = a2 + b2; o.w = a3 + b3;
        *reinterpret_cast<float4*>(dst + (size_t)tp * tstride + (size_t)warp * 64 + cq) = o;
    }
}

// ---------------- generic SGEMM (f32x2 inner) — used for GI projection ----------
__global__ __launch_bounds__(256, 2) void sgemm_kernel(
    const float* __restrict__ A, const float* __restrict__ B, float* __restrict__ C,
    int M, int N, int K, const float* __restrict__ bias, int epi, int transB)
{
    __shared__ __align__(16) float As[8][128];
    __shared__ __align__(16) float Bs[8][128];
    const int tid = threadIdx.x;
    const int bm = blockIdx.y * 128;
    const int bn = blockIdx.x * 128;
    const int tr = (tid / 16) * 8;
    const int tc = (tid % 16) * 8;

    unsigned long long acc2[8][4];
    #pragma unroll
    for (int i = 0; i < 8; i++)
        #pragma unroll
        for (int j = 0; j < 4; j++) acc2[i][j] = 0ull;

    const int arow = tid >> 1;
    const int acol = (tid & 1) * 4;

    for (int kt = 0; kt < K; kt += 8) {
        float4 av = make_float4(0.f, 0.f, 0.f, 0.f);
        if (bm + arow < M)
            av = *reinterpret_cast<const float4*>(A + (size_t)(bm + arow) * K + kt + acol);
        As[acol + 0][arow] = av.x; As[acol + 1][arow] = av.y;
        As[acol + 2][arow] = av.z; As[acol + 3][arow] = av.w;

        if (!transB) {
            int kr = tid >> 5;
            int cc = (tid & 31) * 4;
            float4 bv = make_float4(0.f, 0.f, 0.f, 0.f);
            if (bn + cc < N)
                bv = *reinterpret_cast<const float4*>(B + (size_t)(kt + kr) * N + bn + cc);
            *reinterpret_cast<float4*>(&Bs[kr][cc]) = bv;
        } else {
            int cc = tid >> 1;
            int kk = (tid & 1) * 4;
            float4 bv = make_float4(0.f, 0.f, 0.f, 0.f);
            if (bn + cc < N)
                bv = *reinterpret_cast<const float4*>(B + (size_t)(bn + cc) * K + kt + kk);
            Bs[kk + 0][cc] = bv.x; Bs[kk + 1][cc] = bv.y;
            Bs[kk + 2][cc] = bv.z; Bs[kk + 3][cc] = bv.w;
        }
        __syncthreads();

        #pragma unroll
        for (int k = 0; k < 8; k++) {
            float ar[8];
            *reinterpret_cast<float4*>(ar)     = *reinterpret_cast<const float4*>(&As[k][tr]);
            *reinterpret_cast<float4*>(ar + 4) = *reinterpret_cast<const float4*>(&As[k][tr + 4]);
            ulonglong2 b0 = *reinterpret_cast<const ulonglong2*>(&Bs[k][tc]);
            ulonglong2 b1 = *reinterpret_cast<const ulonglong2*>(&Bs[k][tc + 4]);
            #pragma unroll
            for (int i = 0; i < 8; i++) {
                unsigned long long ad = dup2(ar[i]);
                fma2(acc2[i][0], ad, b0.x);
                fma2(acc2[i][1], ad, b0.y);
                fma2(acc2[i][2], ad, b1.x);
                fma2(acc2[i][3], ad, b1.y);
            }
        }
        __syncthreads();
    }

    #pragma unroll
    for (int i = 0; i < 8; i++) {
        int r = bm + tr + i;
        if (r >= M) continue;
        float acc[8];
        #pragma unroll
        for (int jp = 0; jp < 4; jp++) unpack2(acc2[i][jp], acc[2 * jp], acc[2 * jp + 1]);
        #pragma unroll
        for (int jj = 0; jj < 8; jj += 4) {
            int c = bn + tc + jj;
            if (c >= N) continue;
            float4 v4;
            float* vp = reinterpret_cast<float*>(&v4);
            #pragma unroll
            for (int q = 0; q < 4; q++) {
                float v = acc[jj + q];
                if (epi == 1)      { v += bias[c + q]; v = fmaxf(v, 0.f); }
                else if (epi == 2) { v += bias[c + q]; }
                vp[q] = v;
            }
            *reinterpret_cast<float4*>(C + (size_t)r * N + c) = v4;
        }
    }
}

// ---------------- fused encoder GEMM: P = relu(A@W1 + b1) @ W2 ------------------
// A[M,64], W1[64,128], W2[128,64]. H1 tile (128x128) kept in swizzled smem.
#define FSM_FLOATS (1024 + 1024 + 8192 + 16384)
#define FSM_BYTES  (FSM_FLOATS * 4)

__global__ __launch_bounds__(256) void enc_fused_kernel(
    const float* __restrict__ A, const float* __restrict__ W1, const float* __restrict__ b1,
    const float* __restrict__ W2, float* __restrict__ P, int M)
{
    extern __shared__ __align__(16) float fs[];
    float* As  = fs;          // [8][128] k-major
    float* Bs  = fs + 1024;   // [8][128]
    float* W2s = fs + 2048;   // [128][64]
    float* Hs  = fs + 10240;  // 128x128, XOR-swizzled: (r,k) -> [k*128 + ((r>>2 ^ (k>>3))&31)*4 + (r&3)]
    const int tid = threadIdx.x;
    const int bm = blockIdx.x * 128;

    // load all of W2 (covered by first __syncthreads below)
    for (int i = tid; i < 2048; i += 256)
        reinterpret_cast<float4*>(W2s)[i] = reinterpret_cast<const float4*>(W2)[i];

    // ---- stage 1: H = relu(A @ W1 + b1) ----
    const int tr = (tid / 16) * 8;
    const int tc = (tid % 16) * 8;
    unsigned long long acc2[8][4];
    #pragma unroll
    for (int i = 0; i < 8; i++)
        #pragma unroll
        for (int j = 0; j < 4; j++) acc2[i][j] = 0ull;

    const int arow = tid >> 1;
    const int acol = (tid & 1) * 4;

    #pragma unroll
    for (int kt = 0; kt < 64; kt += 8) {
        float4 av = make_float4(0.f, 0.f, 0.f, 0.f);
        if (bm + arow < M)
            av = *reinterpret_cast<const float4*>(A + (size_t)(bm + arow) * 64 + kt + acol);
        As[(acol + 0) * 128 + arow] = av.x; As[(acol + 1) * 128 + arow] = av.y;
        As[(acol + 2) * 128 + arow] = av.z; As[(acol + 3) * 128 + arow] = av.w;
        {
            int kr = tid >> 5, cc = (tid & 31) * 4;
            *reinterpret_cast<float4*>(&Bs[kr * 128 + cc]) =
                *reinterpret_cast<const float4*>(W1 + (size_t)(kt + kr) * 128 + cc);
        }
        __syncthreads();
        #pragma unroll
        for (int k = 0; k < 8; k++) {
            float ar[8];
            *reinterpret_cast<float4*>(ar)     = *reinterpret_cast<const float4*>(&As[k * 128 + tr]);
            *reinterpret_cast<float4*>(ar + 4) = *reinterpret_cast<const float4*>(&As[k * 128 + tr + 4]);
            ulonglong2 b0 = *reinterpret_cast<const ulonglong2*>(&Bs[k * 128 + tc]);
            ulonglong2 b1v = *reinterpret_cast<const ulonglong2*>(&Bs[k * 128 + tc + 4]);
            #pragma unroll
            for (int i = 0; i < 8; i++) {
                unsigned long long ad = dup2(ar[i]);
                fma2(acc2[i][0], ad, b0.x);
                fma2(acc2[i][1], ad, b0.y);
                fma2(acc2[i][2], ad, b1v.x);
                fma2(acc2[i][3], ad, b1v.y);
            }
        }
        __syncthreads();
    }

    // epilogue: relu+bias -> swizzled Hs
    #pragma unroll
    for (int i = 0; i < 8; i++) {
        int r = tr + i;
        float acc[8];
        #pragma unroll
        for (int jp = 0; jp < 4; jp++) unpack2(acc2[i][jp], acc[2 * jp], acc[2 * jp + 1]);
        #pragma unroll
        for (int j = 0; j < 8; j++) {
            int k = tc + j;
            float v = fmaxf(acc[j] + b1[k], 0.f);
            Hs[k * 128 + ((((r >> 2) ^ (k >> 3)) & 31) << 2) + (r & 3)] = v;
        }
    }
    __syncthreads();

    // ---- stage 2: P_tile = H @ W2 ----
    const int tr2 = (tid >> 3) * 4;
    const int tc2 = (tid & 7) * 8;
    unsigned long long pacc[4][4];
    #pragma unroll
    for (int i = 0; i < 4; i++)
        #pragma unroll
        for (int j = 0; j < 4; j++) pacc[i][j] = 0ull;

    #pragma unroll 8
    for (int k = 0; k < 128; k++) {
        float4 a4 = *reinterpret_cast<const float4*>(
            &Hs[k * 128 + ((((tr2 >> 2) ^ (k >> 3)) & 31) << 2)]);
        ulonglong2 b0 = *reinterpret_cast<const ulonglong2*>(&W2s[k * 64 + tc2]);
        ulonglong2 b1v = *reinterpret_cast<const ulonglong2*>(&W2s[k * 64 + tc2 + 4]);
        float aa[4] = {a4.x, a4.y, a4.z, a4.w};
        #pragma unroll
        for (int i = 0; i < 4; i++) {
            unsigned long long ad = dup2(aa[i]);
            fma2(pacc[i][0], ad, b0.x);
            fma2(pacc[i][1], ad, b0.y);
            fma2(pacc[i][2], ad, b1v.x);
            fma2(pacc[i][3], ad, b1v.y);
        }
    }
    #pragma unroll
    for (int i = 0; i < 4; i++) {
        int r = bm + tr2 + i;
        if (r >= M) continue;
        float o[8];
        #pragma unroll
        for (int jp = 0; jp < 4; jp++) unpack2(pacc[i][jp], o[2 * jp], o[2 * jp + 1]);
        *reinterpret_cast<float4*>(P + (size_t)r * 64 + tc2)     = make_float4(o[0], o[1], o[2], o[3]);
        *reinterpret_cast<float4*>(P + (size_t)r * 64 + tc2 + 4) = make_float4(o[4], o[5], o[6], o[7]);
    }
}

// ---------------- fused GRU: 4 nodes/warp, f32x2; writes h + bf16 split ----------
__global__ __launch_bounds__(256) void gru_fused_kernel(
    const float* __restrict__ gi, const float* __restrict__ Whh,
    const float* __restrict__ bhh, float* __restrict__ h, int N)
{
    __shared__ __align__(16) float4 ws4[3 * 32 * 32];
    const int tid = threadIdx.x;
    for (int idx = tid; idx < 3 * 32 * 32; idx += 256) {
        int lane_ = idx & 31;
        int k2 = (idx >> 5) & 31;
        int g = idx >> 10;
        float4 f;
        f.x = Whh[(size_t)(g * 64 + lane_) * 64 + 2 * k2];
        f.y = Whh[(size_t)(g * 64 + 32 + lane_) * 64 + 2 * k2];
        f.z = Whh[(size_t)(g * 64 + lane_) * 64 + 2 * k2 + 1];
        f.w = Whh[(size_t)(g * 64 + 32 + lane_) * 64 + 2 * k2 + 1];
        ws4[idx] = f;
    }
    __syncthreads();

    const int warp = tid >> 5, lane = tid & 31;
    const int node0 = (blockIdx.x * 8 + warp) * 4;
    if (node0 >= N) return;

    const unsigned long long bR = pack2(bhh[lane],       bhh[32 + lane]);
    const unsigned long long bZ = pack2(bhh[64 + lane],  bhh[96 + lane]);
    const unsigned long long bN = pack2(bhh[128 + lane], bhh[160 + lane]);

    float hA[4] = {0.f, 0.f, 0.f, 0.f}, hB[4] = {0.f, 0.f, 0.f, 0.f};

    const float4* wR = ws4;
    const float4* wZ = ws4 + 32 * 32;
    const float4* wN = ws4 + 2 * 32 * 32;

    #pragma unroll 1
    for (int t = 0; t < T_STEPS; t++) {
        float2 giR[4], giZ[4], giN[4];
        #pragma unroll
        for (int j = 0; j < 4; j++) {
            int node = node0 + j;
            if (node < N) {
                const float* gr = gi + ((size_t)t * N + node) * 192;
                giR[j] = make_float2(gr[lane],       gr[32 + lane]);
                giZ[j] = make_float2(gr[64 + lane],  gr[96 + lane]);
                giN[j] = make_float2(gr[128 + lane], gr[160 + lane]);
            } else {
                giR[j] = giZ[j] = giN[j] = make_float2(0.f, 0.f);
            }
        }

        unsigned long long aR[4], aZ[4], aN[4];
        #pragma unroll
        for (int j = 0; j < 4; j++) { aR[j] = bR; aZ[j] = bZ; aN[j] = bN; }

        if (t > 0) {
            #pragma unroll
            for (int k2 = 0; k2 < 32; k2++) {
                float4 r4 = wR[k2 * 32 + lane];
                float4 z4 = wZ[k2 * 32 + lane];
                float4 n4 = wN[k2 * 32 + lane];
                unsigned long long r0 = pack2(r4.x, r4.y), r1 = pack2(r4.z, r4.w);
                unsigned long long z0 = pack2(z4.x, z4.y), z1 = pack2(z4.z, z4.w);
                unsigned long long n0 = pack2(n4.x, n4.y), n1 = pack2(n4.z, n4.w);
                #pragma unroll
                for (int j = 0; j < 4; j++) {
                    float h0, h1;
                    if (k2 < 16) {
                        h0 = __shfl_sync(FULLM, hA[j], 2 * k2);
                        h1 = __shfl_sync(FULLM, hA[j], 2 * k2 + 1);
                    } else {
                        h0 = __shfl_sync(FULLM, hB[j], 2 * k2 - 32);
                        h1 = __shfl_sync(FULLM, hB[j], 2 * k2 - 31);
                    }
                    unsigned long long d0 = dup2(h0), d1 = dup2(h1);
                    fma2(aR[j], d0, r0); fma2(aR[j], d1, r1);
                    fma2(aZ[j], d0, z0); fma2(aZ[j], d1, z1);
                    fma2(aN[j], d0, n0); fma2(aN[j], d1, n1);
                }
            }
        }

        #pragma unroll
        for (int j = 0; j < 4; j++) {
            float aRlo, aRhi, aZlo, aZhi, aNlo, aNhi;
            unpack2(aR[j], aRlo, aRhi);
            unpack2(aZ[j], aZlo, aZhi);
            unpack2(aN[j], aNlo, aNhi);
            float rg1 = sigm_fast(giR[j].x + aRlo), rg2 = sigm_fast(giR[j].y + aRhi);
            float zg1 = sigm_fast(giZ[j].x + aZlo), zg2 = sigm_fast(giZ[j].y + aZhi);
            float n1 = tanhf(giN[j].x + rg1 * aNlo), n2 = tanhf(giN[j].y + rg2 * aNhi);
            hA[j] = (1.f - zg1) * n1 + zg1 * hA[j];
            hB[j] = (1.f - zg2) * n2 + zg2 * hB[j];
        }
    }

    #pragma unroll
    for (int j = 0; j < 4; j++) {
        int node = node0 + j;
        if (node < N) {
            size_t o1 = (size_t)node * 64 + lane;
            size_t o2 = o1 + 32;
            h[o1] = hA[j]; h[o2] = hB[j];
            __nv_bfloat16 bh1 = __float2bfloat16(hA[j]);
            __nv_bfloat16 bh2 = __float2bfloat16(hB[j]);
            g_hh[o1] = __bfloat16_as_ushort(bh1);
            g_hh[o2] = __bfloat16_as_ushort(bh2);
            g_hl[o1] = __bfloat16_as_ushort(__float2bfloat16(hA[j] - __bfloat162float(bh1)));
            g_hl[o2] = __bfloat16_as_ushort(__float2bfloat16(hB[j] - __bfloat162float(bh2)));
        }
    }
}

// ---------------- decode via warp-level bf16 mma: out = softplus(H H^T + b) ------
#define DSM_AHI 0
#define DSM_ALO 16384
#define DSM_BHI 32768
#define DSM_BLO 49152
#define DSM_TOTAL 65536

__global__ __launch_bounds__(256, 1) void decode_mma_kernel(
    const uint16_t* __restrict__ Hh, const uint16_t* __restrict__ Hl,
    float* __restrict__ out, int N, const float* __restrict__ dec_b)
{
    extern __shared__ __align__(1024) char smem[];
    const uint32_t sb = smem_u32(smem);
    const int tid = threadIdx.x;
    const int wid = tid >> 5, lane = tid & 31;
    const int bm = blockIdx.y * 128;
    const int bn = blockIdx.x * 128;

    {
        const uint16_t* srcs[4]  = { Hh, Hl, Hh, Hl };
        const int       bases[4] = { bm, bm, bn, bn };
        const int       offs[4]  = { DSM_AHI, DSM_ALO, DSM_BHI, DSM_BLO };
        #pragma unroll
        for (int m = 0; m < 4; m++) {
            const uint16_t* s = srcs[m];
            int gb = bases[m], off = offs[m];
            for (int ck = tid; ck < 1024; ck += 256) {
                int row = ck >> 3, cc = ck & 7;
                uint4 v = make_uint4(0u, 0u, 0u, 0u);
                int gr = gb + row;
                if (gr < N) v = *reinterpret_cast<const uint4*>(s + (size_t)gr * 64 + cc * 8);
                int bo = row * 128 + cc * 16;
                *reinterpret_cast<uint4*>(smem + off + SW128(bo)) = v;
            }
        }
    }
    __syncthreads();

    const int mrow = (wid & 1) * 64;
    const int ncol = (wid >> 1) * 32;

    float acc[4][4][4];
    #pragma unroll
    for (int i = 0; i < 4; i++)
        #pragma unroll
        for (int j = 0; j < 4; j++)
            #pragma unroll
            for (int q = 0; q < 4; q++) acc[i][j][q] = 0.f;

    const int a_r  = mrow + (lane & 15);
    const int a_kh = (lane >> 4) * 16;
    // packed B ldmatrix.x4: lane groups of 8 -> (nf, khalf) quadrants
    const int b_rp  = ncol + ((lane >> 4) & 1) * 8 + (lane & 7);
    const int b_khp = ((lane >> 3) & 1) * 16;

    #pragma unroll
    for (int ks = 0; ks < 4; ks++) {
        const int kb = ks * 32;
        uint32_t ah[4][4], al[4][4], bh[4][2], bl[4][2];
        #pragma unroll
        for (int mf = 0; mf < 4; mf++) {
            LDSM4(ah[mf][0], ah[mf][1], ah[mf][2], ah[mf][3],
                  sb + DSM_AHI + SW128((a_r + mf * 16) * 128 + kb + a_kh));
            LDSM4(al[mf][0], al[mf][1], al[mf][2], al[mf][3],
                  sb + DSM_ALO + SW128((a_r + mf * 16) * 128 + kb + a_kh));
        }
        LDSM4(bh[0][0], bh[0][1], bh[1][0], bh[1][1],
              sb + DSM_BHI + SW128(b_rp * 128 + kb + b_khp));
        LDSM4(bh[2][0], bh[2][1], bh[3][0], bh[3][1],
              sb + DSM_BHI + SW128((b_rp + 16) * 128 + kb + b_khp));
        LDSM4(bl[0][0], bl[0][1], bl[1][0], bl[1][1],
              sb + DSM_BLO + SW128(b_rp * 128 + kb + b_khp));
        LDSM4(bl[2][0], bl[2][1], bl[3][0], bl[3][1],
              sb + DSM_BLO + SW128((b_rp + 16) * 128 + kb + b_khp));

        #pragma unroll
        for (int mf = 0; mf < 4; mf++)
            #pragma unroll
            for (int nf = 0; nf < 4; nf++) {
                mma16816(acc[mf][nf], ah[mf], bh[nf]);
                mma16816(acc[mf][nf], ah[mf], bl[nf]);
                mma16816(acc[mf][nf], al[mf], bh[nf]);
            }
    }

    const float bsc = dec_b[0];
    const int rr0 = bm + mrow + (lane >> 2);
    const int cc0 = bn + ncol + 2 * (lane & 3);
    #pragma unroll
    for (int mf = 0; mf < 4; mf++) {
        #pragma unroll
        for (int half = 0; half < 2; half++) {
            int row = rr0 + mf * 16 + half * 8;
            if (row >= N) continue;
            float* orow = out + (size_t)row * N;
            #pragma unroll
            for (int nf = 0; nf < 4; nf++) {
                int col = cc0 + nf * 8;
                if (col + 1 >= N && col >= N) continue;
                float v0 = acc[mf][nf][half * 2 + 0] + bsc;
                float v1 = acc[mf][nf][half * 2 + 1] + bsc;
                float e0 = __expf(-fabsf(v0)), e1 = __expf(-fabsf(v1));
                float2 o;
                o.x = fmaxf(v0, 0.f) + __logf(1.f + e0);
                o.y = fmaxf(v1, 0.f) + __logf(1.f + e1);
                if (col + 1 < N) {
                    *reinterpret_cast<float2*>(orow + col) = o;
                } else if (col < N) {
                    orow[col] = o.x;
                }
            }
        }
    }
}

__global__ void copy_z_kernel(float* __restrict__ out, int n) {
    int i = blockIdx.x * blockDim.x + threadIdx.x;
    if (i < n) out[i] = g_h[i];
}

// ---------------- launch ----------------
extern "C" void kernel_launch(void* const* d_in, const int* in_sizes, int n_in,
                              void* d_out, int out_size) {
    const float* x_seq  = (const float*)d_in[0];
    const void*  ei     = d_in[1];
    const float* ew     = (const float*)d_in[2];
    const float* W1     = (const float*)d_in[3];
    const float* b1     = (const float*)d_in[4];
    const float* W2     = (const float*)d_in[5];
    const float* b2     = (const float*)d_in[6];
    const float* W_ih   = (const float*)d_in[7];
    const float* W_hh   = (const float*)d_in[8];
    const float* b_ih   = (const float*)d_in[9];
    const float* b_hh   = (const float*)d_in[10];
    const float* dec_b  = (const float*)d_in[11];

    const int E = in_sizes[2];
    const int N = in_sizes[0] / (T_STEPS * IN_DIM);
    const int MT = T_STEPS * N;
    float* out = (float*)d_out;

    float *p_aggx, *p_zseq, *p_gi, *p_h;
    uint16_t *p_hh, *p_hl;
    cudaGetSymbolAddress((void**)&p_aggx, g_aggx);
    cudaGetSymbolAddress((void**)&p_zseq, g_zseq);
    cudaGetSymbolAddress((void**)&p_gi,   g_gi);
    cudaGetSymbolAddress((void**)&p_h,    g_h);
    cudaGetSymbolAddress((void**)&p_hh,   g_hh);
    cudaGetSymbolAddress((void**)&p_hl,   g_hl);

    cudaFuncSetAttribute(decode_mma_kernel, cudaFuncAttributeMaxDynamicSharedMemorySize, DSM_TOTAL);
    cudaFuncSetAttribute(enc_fused_kernel,  cudaFuncAttributeMaxDynamicSharedMemorySize, FSM_BYTES);

    // --- preprocessing ---
    zero_pre_kernel<<<(N + 255) / 256, 256>>>(N);
    detect_kernel<<<(E + 255) / 256, 256>>>(ei, E, N);
    deg_kernel<<<(E + N + 255) / 256, 256>>>(ei, ew, E, N);
    dinv_kernel<<<(N + 255) / 256, 256>>>(N);
    scan_kernel<<<1, 1024>>>(N);
    scatter_kernel<<<(E + N + 255) / 256, 256>>>(ei, ew, E, N);

    const int aggBlocks = (N * 32 + 255) / 256;

    // --- encoder, batched over all T ---
    agg_kernel<<<aggBlocks, 256>>>(x_seq, p_aggx, nullptr, N);
    // P = relu(aggx@W1+b1)@W2, fused; write into zseq buffer temporarily? No —
    // write into g_gi region? P must survive until agg2 reads it. Use p_zseq as P,
    // then agg2 reads p_zseq and writes ... into p_aggx (free by then).
    enc_fused_kernel<<<(MT + 127) / 128, 256, FSM_BYTES>>>(p_aggx, W1, b1, W2, p_zseq, MT);
    agg_kernel<<<aggBlocks, 256>>>(p_zseq, p_aggx, b2, N);   // zseq_final -> p_aggx

    // --- GRU: GI = zseq_final @ W_ih^T + b_ih ---
    {
        dim3 g(2, (MT + 127) / 128);
        sgemm_kernel<<<g, 256>>>(p_aggx, W_ih, p_gi, MT, 3 * EMB_DIM, EMB_DIM, b_ih, 2, 1);
    }
    gru_fused_kernel<<<(N + 31) / 32, 256>>>(p_gi, W_hh, b_hh, p_h, N);

    // --- decode via warp-mma bf16-split (hh/hl written by GRU) ---
    {
        dim3 g((N + 127) / 128, (N + 127) / 128);
        decode_mma_kernel<<<g, 256, DSM_TOTAL>>>(p_hh, p_hl, out, N, dec_b);
    }
    if ((long long)out_size >= (long long)N * N + (long long)N * EMB_DIM) {
        copy_z_kernel<<<(N * EMB_DIM + 255) / 256, 256>>>(out + (size_t)N * N, N * EMB_DIM);
    }
}